// round 14
// baseline (speedup 1.0000x reference)
#include <cuda_runtime.h>
#include <cuda_bf16.h>
#include <math.h>
#include <stdint.h>

// ---------------- problem constants ----------------
constexpr int CB    = 2;
constexpr int CQ    = 1024;
constexpr int CHID  = 2048;
constexpr int CNH   = 32;
constexpr int CNKV  = 8;
constexpr int CHD   = 64;
constexpr int CG    = 4;
constexpr int CKB   = 512;
constexpr int CTOPK = 100;
#define SCALE_L2E 0.18033688f     // 0.125 * log2(e)
#define KB_B2     2.3561430f      // log2(512/100)

// ---------------- selection scratch ----------------
__device__ float g_hssum_part[CB*8*CHID];
__device__ float g_qg_part[CB*64*512];
__device__ float g_qg[CB*512];
__device__ float g_v[CB*CHID];
__device__ float g_scores[CB*CKB];
__device__ int   g_topidx[CB*CTOPK];

// ---------------- bf16 hi/lo buffers ----------------
__device__ __nv_bfloat16 s_hs_h [CB*CQ*CHID],  s_hs_l [CB*CQ*CHID];
__device__ __nv_bfloat16 s_kb_h [CB*CKB*CHID], s_kb_l [CB*CKB*CHID];
__device__ __nv_bfloat16 s_at_h [CB*CQ*CHID],  s_at_l [CB*CQ*CHID];
__device__ __nv_bfloat16 s_wcomb_h[CHID*5120], s_wcomb_l[CHID*5120]; // [K][Wq|Wqn|Wk|Wv]
__device__ __nv_bfloat16 s_wo_h [CHID*CHID],   s_wo_l [CHID*CHID];
__device__ __nv_bfloat16 s_wkb_h[CHID*1024],   s_wkb_l[CHID*1024];   // [K][Wkbk|Wkbv]
// attention operands
__device__ __nv_bfloat16 s_qh  [CB*CQ*CHID],   s_ql  [CB*CQ*CHID];
__device__ __nv_bfloat16 s_kbqh[CB*CQ*CHID],   s_kbql[CB*CQ*CHID];
__device__ __nv_bfloat16 s_kvh [CB*CQ*1024],   s_kvl [CB*CQ*1024];
__device__ __nv_bfloat16 s_kbkvh[CB*CKB*1024], s_kbkvl[CB*CKB*1024];

// ---------------- common PTX helpers ----------------
__device__ __forceinline__ void cp_async16(uint32_t dst, const void* src) {
    asm volatile("cp.async.cg.shared.global [%0], [%1], 16;\n" :: "r"(dst), "l"(src));
}
__device__ __forceinline__ void mma16816(float* c, const unsigned* a, const unsigned* b) {
    asm volatile(
        "mma.sync.aligned.m16n8k16.row.col.f32.bf16.bf16.f32 "
        "{%0,%1,%2,%3}, {%4,%5,%6,%7}, {%8,%9}, {%0,%1,%2,%3};"
        : "+f"(c[0]), "+f"(c[1]), "+f"(c[2]), "+f"(c[3])
        : "r"(a[0]), "r"(a[1]), "r"(a[2]), "r"(a[3]), "r"(b[0]), "r"(b[1]));
}
#define LDSM4(R, addr) asm volatile( \
    "ldmatrix.sync.aligned.m8n8.x4.shared.b16 {%0,%1,%2,%3}, [%4];" \
    : "=r"((R)[0]), "=r"((R)[1]), "=r"((R)[2]), "=r"((R)[3]) : "r"(addr))
#define LDSM4T(R, addr) asm volatile( \
    "ldmatrix.sync.aligned.m8n8.x4.trans.shared.b16 {%0,%1,%2,%3}, [%4];" \
    : "=r"((R)[0]), "=r"((R)[1]), "=r"((R)[2]), "=r"((R)[3]) : "r"(addr))
__device__ __forceinline__ float fexp2(float x) {
    float y; asm("ex2.approx.ftz.f32 %0, %1;" : "=f"(y) : "f"(x)); return y;
}

// ---------------- split helpers ----------------
__device__ __forceinline__ void split8_store(const float* __restrict__ s4base, int i,
                                             __nv_bfloat16* dh, __nv_bfloat16* dl, size_t ob) {
    const float4* s4 = (const float4*)s4base;
    float4 a = s4[i * 2], b4 = s4[i * 2 + 1];
    float vv[8] = {a.x, a.y, a.z, a.w, b4.x, b4.y, b4.z, b4.w};
    __nv_bfloat162 H[4], L[4];
    #pragma unroll
    for (int j = 0; j < 4; j++) {
        __nv_bfloat16 h0 = __float2bfloat16_rn(vv[2*j]);
        __nv_bfloat16 h1 = __float2bfloat16_rn(vv[2*j+1]);
        H[j] = __nv_bfloat162(h0, h1);
        L[j] = __nv_bfloat162(__float2bfloat16_rn(vv[2*j]   - __bfloat162float(h0)),
                              __float2bfloat16_rn(vv[2*j+1] - __bfloat162float(h1)));
    }
    *(uint4*)&dh[ob] = *(uint4*)H;
    *(uint4*)&dl[ob] = *(uint4*)L;
}

// mega split minus Wo (9216 blocks)
__global__ __launch_bounds__(256)
void splitall_kernel(const float* __restrict__ hs, const float* __restrict__ kb,
                     const float* __restrict__ Wq, const float* __restrict__ Wk,
                     const float* __restrict__ Wv,
                     const float* __restrict__ Wqn, const float* __restrict__ Wkbk,
                     const float* __restrict__ Wkbv) {
    int bid = blockIdx.x;
    const float* src; __nv_bfloat16 *dh, *dl;
    int c8pr, ostr, coff;
    if      (bid <  2048) {               src = hs;   dh = s_hs_h;    dl = s_hs_l;    c8pr = 256; ostr = 2048; coff = 0;    }
    else if (bid <  3072) { bid -= 2048;  src = kb;   dh = s_kb_h;    dl = s_kb_l;    c8pr = 256; ostr = 2048; coff = 0;    }
    else if (bid <  5120) { bid -= 3072;  src = Wq;   dh = s_wcomb_h; dl = s_wcomb_l; c8pr = 256; ostr = 5120; coff = 0;    }
    else if (bid <  7168) { bid -= 5120;  src = Wqn;  dh = s_wcomb_h; dl = s_wcomb_l; c8pr = 256; ostr = 5120; coff = 2048; }
    else if (bid <  7680) { bid -= 7168;  src = Wk;   dh = s_wcomb_h; dl = s_wcomb_l; c8pr = 64;  ostr = 5120; coff = 4096; }
    else if (bid <  8192) { bid -= 7680;  src = Wv;   dh = s_wcomb_h; dl = s_wcomb_l; c8pr = 64;  ostr = 5120; coff = 4608; }
    else if (bid <  8704) { bid -= 8192;  src = Wkbk; dh = s_wkb_h;   dl = s_wkb_l;   c8pr = 64;  ostr = 1024; coff = 0;    }
    else                  { bid -= 8704;  src = Wkbv; dh = s_wkb_h;   dl = s_wkb_l;   c8pr = 64;  ostr = 1024; coff = 512;  }

    int i = bid * 256 + threadIdx.x;      // float8 index
    int r = i / c8pr, c8 = i % c8pr;
    split8_store(src, i, dh, dl, (size_t)r * ostr + coff + c8 * 8);
}

// Wo split (runs on s2 in proj's shadow)
__global__ __launch_bounds__(256)
void wosplit_kernel(const float* __restrict__ Wo) {
    int i = blockIdx.x * 256 + threadIdx.x;
    split8_store(Wo, i, s_wo_h, s_wo_l, (size_t)i * 8);
}

// ---------------- shared GEMM machinery ----------------
constexpr int GBK = 32, GSTG = 3;
constexpr int STAGE_BYTES = 32768;

__device__ __forceinline__ void gemm_issue_stage(
        uint32_t base, int tid,
        const __nv_bfloat16* Ah, const __nv_bfloat16* Al,
        const __nv_bfloat16* Bh, const __nv_bfloat16* Bl,
        int rb, int cb, int k0, int K, int N) {
    #pragma unroll
    for (int it = 0; it < 2; it++) {
        int i = tid + it * 256;
        int r = i >> 2, c = i & 3;
        uint32_t dst = base + r * 64 + (((c ^ ((r >> 1) & 3))) << 4);
        size_t so = (size_t)(rb + r) * K + k0 + c * 8;
        cp_async16(dst,        Ah + so);
        cp_async16(dst + 8192, Al + so);
    }
    #pragma unroll
    for (int it = 0; it < 2; it++) {
        int i = tid + it * 256;
        int r = i >> 4, cn = i & 15;
        uint32_t dst = base + 16384 + r * 256 + (((cn ^ (r & 7))) << 4);
        size_t so = (size_t)(k0 + r) * N + cb + cn * 8;
        cp_async16(dst,        Bh + so);
        cp_async16(dst + 8192, Bl + so);
    }
}

__device__ __forceinline__ void gemm_mainloop(
        uint32_t sb, int tid, int lane, int wm, int wn,
        const __nv_bfloat16* Ah, const __nv_bfloat16* Al,
        const __nv_bfloat16* Bh, const __nv_bfloat16* Bl,
        int rb, int cb, int K, int N, float (&acc)[2][8][4]) {
    const int nk = K / GBK;
    gemm_issue_stage(sb, tid, Ah, Al, Bh, Bl, rb, cb, 0, K, N);
    asm volatile("cp.async.commit_group;\n" ::);
    if (nk > 1) {
        gemm_issue_stage(sb + STAGE_BYTES, tid, Ah, Al, Bh, Bl, rb, cb, GBK, K, N);
    }
    asm volatile("cp.async.commit_group;\n" ::);

    const int sub = lane >> 3, li = lane & 7;
    const int arow_off = ((sub & 1) ? 8 : 0) + li;
    const int akc_off  = (sub >> 1) ? 8 : 0;
    const int bk_off   = ((sub & 1) ? 8 : 0) + li;
    const int bn_off   = (sub >> 1) ? 8 : 0;

    for (int i = 0; i < nk; i++) {
        asm volatile("cp.async.wait_group 1;\n" ::);
        __syncthreads();
        const int st = i % GSTG;
        const uint32_t abase = sb + st * STAGE_BYTES;
        const uint32_t bbase = abase + 16384;
        if (i + 2 < nk)
            gemm_issue_stage(sb + ((i + 2) % GSTG) * STAGE_BYTES, tid,
                             Ah, Al, Bh, Bl, rb, cb, (i + 2) * GBK, K, N);
        asm volatile("cp.async.commit_group;\n" ::);

        #pragma unroll
        for (int kk = 0; kk < GBK; kk += 16) {
            unsigned bh[8][2], bl[8][2];
            #pragma unroll
            for (int np = 0; np < 4; np++) {
                int n0 = wn * 64 + np * 16;
                int k  = kk + bk_off;
                int n  = n0 + bn_off;
                uint32_t addr = bbase + k * 256 + ((((n >> 3) ^ (k & 7))) << 4);
                unsigned r_[4];
                LDSM4T(r_, addr);
                bh[np*2][0] = r_[0]; bh[np*2][1] = r_[1]; bh[np*2+1][0] = r_[2]; bh[np*2+1][1] = r_[3];
                LDSM4T(r_, addr + 8192);
                bl[np*2][0] = r_[0]; bl[np*2][1] = r_[1]; bl[np*2+1][0] = r_[2]; bl[np*2+1][1] = r_[3];
            }
            #pragma unroll
            for (int mt = 0; mt < 2; mt++) {
                int r0 = wm * 32 + mt * 16;
                int row  = r0 + arow_off;
                int kcol = kk + akc_off;
                uint32_t aaddr = abase + row * 64 + ((((kcol >> 3) ^ ((row >> 1) & 3))) << 4);
                unsigned ah[4], al[4];
                LDSM4(ah, aaddr);
                LDSM4(al, aaddr + 8192);
                #pragma unroll
                for (int nt = 0; nt < 8; nt++) {
                    mma16816(acc[mt][nt], ah, bh[nt]);
                    mma16816(acc[mt][nt], ah, bl[nt]);
                    mma16816(acc[mt][nt], al, bh[nt]);
                }
            }
        }
        __syncthreads();
    }
}

__device__ __forceinline__ void rope_acc(float (&a)[8][4], int p0, int p1, int tig,
                                         const float* __restrict__ cosT,
                                         const float* __restrict__ sinT) {
    #pragma unroll
    for (int nt = 0; nt < 4; nt++) {
        const int d0 = nt * 8 + 2 * tig;
        float2 c0l = *(const float2*)&cosT[p0 + d0];
        float2 s0l = *(const float2*)&sinT[p0 + d0];
        float2 c0h = *(const float2*)&cosT[p0 + d0 + 32];
        float2 s0h = *(const float2*)&sinT[p0 + d0 + 32];
        float2 c1l = *(const float2*)&cosT[p1 + d0];
        float2 s1l = *(const float2*)&sinT[p1 + d0];
        float2 c1h = *(const float2*)&cosT[p1 + d0 + 32];
        float2 s1h = *(const float2*)&sinT[p1 + d0 + 32];
        float x1, x2;
        x1 = a[nt][0]; x2 = a[nt+4][0];
        a[nt][0]   = x1 * c0l.x - x2 * s0l.x;
        a[nt+4][0] = x2 * c0h.x + x1 * s0h.x;
        x1 = a[nt][1]; x2 = a[nt+4][1];
        a[nt][1]   = x1 * c0l.y - x2 * s0l.y;
        a[nt+4][1] = x2 * c0h.y + x1 * s0h.y;
        x1 = a[nt][2]; x2 = a[nt+4][2];
        a[nt][2]   = x1 * c1l.x - x2 * s1l.x;
        a[nt+4][2] = x2 * c1h.x + x1 * s1h.x;
        x1 = a[nt][3]; x2 = a[nt+4][3];
        a[nt][3]   = x1 * c1l.y - x2 * s1l.y;
        a[nt+4][3] = x2 * c1h.y + x1 * s1h.y;
    }
}

__device__ __forceinline__ void split_write(__nv_bfloat16* Oh, __nv_bfloat16* Ol,
                                            size_t off, float a, float b) {
    __nv_bfloat162 h = __floats2bfloat162_rn(a, b);
    float2 f = __bfloat1622float2(h);
    __nv_bfloat162 l = __floats2bfloat162_rn(a - f.x, b - f.y);
    *(__nv_bfloat162*)&Oh[off] = h;
    *(__nv_bfloat162*)&Ol[off] = l;
}

// ---------------- merged projection GEMM ----------------
__global__ __launch_bounds__(256)
void proj_gemm(const int* __restrict__ pos,
               const float* __restrict__ cosT, const float* __restrict__ sinT) {
    extern __shared__ char smem[];
    uint32_t sb = (uint32_t)__cvta_generic_to_shared(smem);
    const int tid = threadIdx.x, lane = tid & 31, wid = tid >> 5;
    const int wm = wid >> 1, wn = wid & 1;
    const int gid = lane >> 2, tig = lane & 3;

    const bool iskb = blockIdx.x >= 640;
    int bx, by, N;
    const __nv_bfloat16 *Ah, *Al, *Bh, *Bl;
    if (!iskb) {
        bx = blockIdx.x % 40; by = blockIdx.x / 40; N = 5120;
        Ah = s_hs_h; Al = s_hs_l; Bh = s_wcomb_h; Bl = s_wcomb_l;
    } else {
        int idx = blockIdx.x - 640;
        bx = idx % 8; by = idx / 8; N = 1024;
        Ah = s_kb_h; Al = s_kb_l; Bh = s_wkb_h; Bl = s_wkb_l;
    }
    const int rb = by * 128, cb = bx * 128;

    float acc[2][8][4];
    #pragma unroll
    for (int mt = 0; mt < 2; mt++)
        #pragma unroll
        for (int nt = 0; nt < 8; nt++)
            #pragma unroll
            for (int i = 0; i < 4; i++) acc[mt][nt][i] = 0.f;

    gemm_mainloop(sb, tid, lane, wm, wn, Ah, Al, Bh, Bl, rb, cb, CHID, N, acc);

    const int colbase = cb + wn * 64;
    #pragma unroll
    for (int mt = 0; mt < 2; mt++) {
        const int row0 = rb + wm * 32 + mt * 16 + gid;
        const int row1 = row0 + 8;
        if (iskb) {
            #pragma unroll
            for (int nt = 0; nt < 8; nt++) {
                const int col = colbase + nt * 8 + tig * 2;
                split_write(s_kbkvh, s_kbkvl, (size_t)row0 * 1024 + col, acc[mt][nt][0], acc[mt][nt][1]);
                split_write(s_kbkvh, s_kbkvl, (size_t)row1 * 1024 + col, acc[mt][nt][2], acc[mt][nt][3]);
            }
        } else if (colbase < 2048) {
            rope_acc(acc[mt], pos[row0] * 64, pos[row1] * 64, tig, cosT, sinT);
            #pragma unroll
            for (int nt = 0; nt < 8; nt++) {
                const int col = colbase + nt * 8 + tig * 2;
                split_write(s_qh, s_ql, (size_t)row0 * 2048 + col,
                            acc[mt][nt][0] * SCALE_L2E, acc[mt][nt][1] * SCALE_L2E);
                split_write(s_qh, s_ql, (size_t)row1 * 2048 + col,
                            acc[mt][nt][2] * SCALE_L2E, acc[mt][nt][3] * SCALE_L2E);
            }
        } else if (colbase < 4096) {
            #pragma unroll
            for (int nt = 0; nt < 8; nt++) {
                const int col = colbase - 2048 + nt * 8 + tig * 2;
                split_write(s_kbqh, s_kbql, (size_t)row0 * 2048 + col,
                            acc[mt][nt][0] * SCALE_L2E, acc[mt][nt][1] * SCALE_L2E);
                split_write(s_kbqh, s_kbql, (size_t)row1 * 2048 + col,
                            acc[mt][nt][2] * SCALE_L2E, acc[mt][nt][3] * SCALE_L2E);
            }
        } else {
            if (colbase < 4608)
                rope_acc(acc[mt], pos[row0] * 64, pos[row1] * 64, tig, cosT, sinT);
            #pragma unroll
            for (int nt = 0; nt < 8; nt++) {
                const int col = colbase - 4096 + nt * 8 + tig * 2;
                split_write(s_kvh, s_kvl, (size_t)row0 * 1024 + col, acc[mt][nt][0], acc[mt][nt][1]);
                split_write(s_kvh, s_kvl, (size_t)row1 * 1024 + col, acc[mt][nt][2], acc[mt][nt][3]);
            }
        }
    }
}

// ---------------- output GEMM ----------------
__global__ __launch_bounds__(256)
void wo_gemm(float* __restrict__ Cf, int M, int N, int K) {
    extern __shared__ char smem[];
    uint32_t sb = (uint32_t)__cvta_generic_to_shared(smem);
    const int tid = threadIdx.x, lane = tid & 31, wid = tid >> 5;
    const int wm = wid >> 1, wn = wid & 1;
    const int gid = lane >> 2, tig = lane & 3;
    const int rb = blockIdx.y * 128, cb = blockIdx.x * 128;

    float acc[2][8][4];
    #pragma unroll
    for (int mt = 0; mt < 2; mt++)
        #pragma unroll
        for (int nt = 0; nt < 8; nt++)
            #pragma unroll
            for (int i = 0; i < 4; i++) acc[mt][nt][i] = 0.f;

    gemm_mainloop(sb, tid, lane, wm, wn, s_at_h, s_at_l, s_wo_h, s_wo_l, rb, cb, K, N, acc);

    #pragma unroll
    for (int mt = 0; mt < 2; mt++) {
        int r = rb + wm * 32 + mt * 16;
        #pragma unroll
        for (int nt = 0; nt < 8; nt++) {
            int c = cb + wn * 64 + nt * 8 + tig * 2;
            *(float2*)&Cf[(size_t)(r + gid    ) * N + c] = make_float2(acc[mt][nt][0], acc[mt][nt][1]);
            *(float2*)&Cf[(size_t)(r + gid + 8) * N + c] = make_float2(acc[mt][nt][2], acc[mt][nt][3]);
        }
    }
}

// ---------------- factored KB selection ----------------
__global__ void hssum_kernel(const float* __restrict__ hs) {
    int b = blockIdx.x, c = blockIdx.y * 128 + threadIdx.x, qz = blockIdx.z;
    float s = 0.f;
    const float* p = hs + (size_t)b * CQ * CHID + (size_t)qz * 128 * CHID + c;
    #pragma unroll 8
    for (int q = 0; q < 128; q++) s += p[(size_t)q * CHID];
    g_hssum_part[(b * 8 + qz) * CHID + c] = s;
}

__global__ __launch_bounds__(512) void qg_kernel(const float* __restrict__ Wqn) {
    __shared__ float hsum[CHID];
    int b = blockIdx.x, z = blockIdx.y, c = threadIdx.x;   // c = 0..511
    #pragma unroll
    for (int cc = 0; cc < 4; cc++) {
        int col = cc * 512 + c;
        float s = 0.f;
        #pragma unroll
        for (int qz = 0; qz < 8; qz++) s += g_hssum_part[(b * 8 + qz) * CHID + col];
        hsum[col] = s;
    }
    __syncthreads();
    int kh = c >> 6, d = c & 63;
    float s = 0.f;
    #pragma unroll 4
    for (int j = z * 32; j < z * 32 + 32; j++) {
        const float* wr = Wqn + (size_t)j * CHID + kh * 256 + d;
        s = fmaf(hsum[j], wr[0] + wr[64] + wr[128] + wr[192], s);
    }
    g_qg_part[(b * 64 + z) * 512 + c] = s;
}
__global__ void qgc_kernel() {
    int b = blockIdx.x, c = threadIdx.x;   // 512 threads
    float s = 0.f;
    #pragma unroll
    for (int z = 0; z < 64; z++) s += g_qg_part[(b * 64 + z) * 512 + c];
    g_qg[b * 512 + c] = s;
}

__global__ __launch_bounds__(256) void vk_kernel(const float* __restrict__ Wkbk) {
    __shared__ float qs[512];
    int b = blockIdx.x;
    for (int c = threadIdx.x; c < 512; c += 256) qs[c] = g_qg[b * 512 + c];
    __syncthreads();
    int w = threadIdx.x >> 5, l = threadIdx.x & 31;
    int jbase = blockIdx.y * 16 + w * 2;
    #pragma unroll
    for (int jj = 0; jj < 2; jj++) {
        int j = jbase + jj;
        float s = 0.f;
        #pragma unroll
        for (int c = l; c < 512; c += 32) s = fmaf(Wkbk[(size_t)j * 512 + c], qs[c], s);
        #pragma unroll
        for (int o = 16; o > 0; o >>= 1) s += __shfl_xor_sync(0xffffffffu, s, o);
        if (l == 0) g_v[b * CHID + j] = s;
    }
}

__global__ void scores_kernel(const float* __restrict__ kb) {
    int gw = blockIdx.x * 8 + (threadIdx.x >> 5);
    int l  = threadIdx.x & 31;
    int b  = gw >> 9, n = gw & 511;
    const float* kr = kb + (size_t)(b * CKB + n) * CHID;
    const float* vv = g_v + b * CHID;
    float s = 0.f;
    #pragma unroll 8
    for (int i = l; i < CHID; i += 32) s = fmaf(kr[i], vv[i], s);
    #pragma unroll
    for (int o = 16; o > 0; o >>= 1) s += __shfl_xor_sync(0xffffffffu, s, o);
    if (l == 0) g_scores[b * CKB + n] = s;
}

__global__ void topk_kernel() {
    int b = blockIdx.x, l = threadIdx.x;
    float vreg[16];
    #pragma unroll
    for (int s = 0; s < 16; s++) vreg[s] = g_scores[b * CKB + s * 32 + l];
    for (int t = 0; t < CTOPK; t++) {
        float v = vreg[0]; int idx = l;
        #pragma unroll
        for (int s = 1; s < 16; s++) {
            float x = vreg[s]; int xi = s * 32 + l;
            if (x > v || (x == v && xi < idx)) { v = x; idx = xi; }
        }
        #pragma unroll
        for (int o = 16; o > 0; o >>= 1) {
            float ov = __shfl_xor_sync(0xffffffffu, v, o);
            int   oi = __shfl_xor_sync(0xffffffffu, idx, o);
            if (ov > v || (ov == v && oi < idx)) { v = ov; idx = oi; }
        }
        if (l == 0) g_topidx[b * CTOPK + t] = idx;
        if ((idx & 31) == l) vreg[idx >> 5] = -3.0e38f;
    }
}

// ---------------- tensor-core fused flash attention (128-q tile, 256 threads) ----------------
// smem: Qh 16K | Ql 16K | 2 stages x { Kh 8K | Kl 8K | Vh 8K | Vl 8K }
constexpr int ATT_SMEM = 32768 + 2 * 32768;

__device__ __forceinline__ void attn_load_tile(uint32_t st, int b, int kh, int ph2, int t, int tid) {
    for (int i = tid; i < 512; i += 256) {
        int r = i >> 3, c = i & 7;
        int kg = t * 64 + r;
        const __nv_bfloat16 *H, *L;
        size_t base;
        if (ph2 == 0) {
            int n = (kg < CTOPK) ? g_topidx[b * CTOPK + kg] : 0;
            base = (size_t)(b * CKB + n) * 1024 + kh * 64;
            H = s_kbkvh; L = s_kbkvl;
        } else {
            base = (size_t)(b * CQ + kg) * 1024 + kh * 64;
            H = s_kvh; L = s_kvl;
        }
        uint32_t d = st + r * 128 + ((c ^ (r & 7)) << 4);
        cp_async16(d,         H + base + c * 8);
        cp_async16(d + 8192,  L + base + c * 8);
        cp_async16(d + 16384, H + base + 512 + c * 8);
        cp_async16(d + 24576, L + base + 512 + c * 8);
    }
}

__global__ __launch_bounds__(256) void attn_tc_kernel() {
    extern __shared__ char asmem[];
    uint32_t sq = (uint32_t)__cvta_generic_to_shared(asmem);
    const int tid = threadIdx.x, lane = tid & 31, w = tid >> 5;   // 8 warps
    const int gid = lane >> 2, tig = lane & 3;
    const int sub = lane >> 3, li = lane & 7;
    const int qt = (int)(gridDim.x - 1 - blockIdx.x);   // longest-first scheduling
    const int h = blockIdx.y, b = blockIdx.z;
    const int kh = h >> 2;
    const int q0 = qt * 128;

    float m0 = -1e30f, m1 = -1e30f, l0 = 0.f, l1 = 0.f;
    float oacc[8][4];
    #pragma unroll
    for (int nt = 0; nt < 8; nt++)
        #pragma unroll
        for (int c = 0; c < 4; c++) oacc[nt][c] = 0.f;

    for (int ph2 = 0; ph2 < 2; ph2++) {
        __syncthreads();
        const __nv_bfloat16* Qh = ph2 ? s_qh : s_kbqh;
        const __nv_bfloat16* Ql = ph2 ? s_ql : s_kbql;
        for (int i = tid; i < 1024; i += 256) {       // 128 rows x 8 chunks
            int r = i >> 3, c = i & 7;
            uint32_t dst = sq + r * 128 + ((c ^ (r & 7)) << 4);
            size_t src = (size_t)(b * CQ + q0 + r) * 2048 + h * 64 + c * 8;
            cp_async16(dst,         Qh + src);
            cp_async16(dst + 16384, Ql + src);
        }
        const int ntiles = ph2 ? (2 * qt + 2) : 2;
        attn_load_tile(sq + 32768, b, kh, ph2, 0, tid);
        asm volatile("cp.async.commit_group;\n" ::);

        for (int t = 0; t < ntiles; t++) {
            asm volatile("cp.async.wait_group 0;\n" ::);
            __syncthreads();
            if (t + 1 < ntiles) {
                attn_load_tile(sq + 32768 + ((t + 1) & 1) * 32768, b, kh, ph2, t + 1, tid);
                asm volatile("cp.async.commit_group;\n" ::);
            }
            const uint32_t stK = sq + 32768 + (t & 1) * 32768;
            const uint32_t stV = stK + 16384;

            float sacc[8][4];
            #pragma unroll
            for (int nt = 0; nt < 8; nt++)
                #pragma unroll
                for (int c = 0; c < 4; c++) sacc[nt][c] = 0.f;

            #pragma unroll
            for (int k16 = 0; k16 < 4; k16++) {
                int kk = k16 * 16;
                unsigned qa_h[4], qa_l[4];
                {
                    int row = w * 16 + (sub & 1) * 8 + li;
                    int ch  = (kk >> 3) + (sub >> 1);
                    uint32_t a = sq + row * 128 + ((ch ^ (row & 7)) << 4);
                    LDSM4(qa_h, a);
                    LDSM4(qa_l, a + 16384);
                }
                unsigned kb_h[8][2], kb_l[8][2];
                #pragma unroll
                for (int nt2 = 0; nt2 < 4; nt2++) {
                    int n  = nt2 * 16 + (sub >> 1) * 8 + li;
                    int ch = (kk >> 3) + (sub & 1);
                    uint32_t a = stK + n * 128 + ((ch ^ (n & 7)) << 4);
                    unsigned r_[4];
                    LDSM4(r_, a);
                    kb_h[nt2*2][0] = r_[0]; kb_h[nt2*2][1] = r_[1];
                    kb_h[nt2*2+1][0] = r_[2]; kb_h[nt2*2+1][1] = r_[3];
                    LDSM4(r_, a + 8192);
                    kb_l[nt2*2][0] = r_[0]; kb_l[nt2*2][1] = r_[1];
                    kb_l[nt2*2+1][0] = r_[2]; kb_l[nt2*2+1][1] = r_[3];
                }
                #pragma unroll
                for (int nt = 0; nt < 8; nt++) {
                    mma16816(sacc[nt], qa_h, kb_h[nt]);
                    mma16816(sacc[nt], qa_h, kb_l[nt]);
                    mma16816(sacc[nt], qa_l, kb_h[nt]);
                }
            }

            if (ph2 == 0) {
                #pragma unroll
                for (int nt = 0; nt < 8; nt++) {
                    int kg = t * 64 + nt * 8 + 2 * tig;
                    sacc[nt][0] = (kg     < CTOPK) ? sacc[nt][0] + KB_B2 : -1e30f;
                    sacc[nt][1] = (kg + 1 < CTOPK) ? sacc[nt][1] + KB_B2 : -1e30f;
                    sacc[nt][2] = (kg     < CTOPK) ? sacc[nt][2] + KB_B2 : -1e30f;
                    sacc[nt][3] = (kg + 1 < CTOPK) ? sacc[nt][3] + KB_B2 : -1e30f;
                }
            } else if (t >= 2 * qt) {
                // diagonal tiles: elementwise causal mask (no-op for fully visible rows)
                int rq0 = q0 + w * 16 + gid, rq1 = rq0 + 8;
                #pragma unroll
                for (int nt = 0; nt < 8; nt++) {
                    int kg = t * 64 + nt * 8 + 2 * tig;
                    if (kg     > rq0) sacc[nt][0] = -1e30f;
                    if (kg + 1 > rq0) sacc[nt][1] = -1e30f;
                    if (kg     > rq1) sacc[nt][2] = -1e30f;
                    if (kg + 1 > rq1) sacc[nt][3] = -1e30f;
                }
            }

            float mx0 = -1e30f, mx1 = -1e30f;
            #pragma unroll
            for (int nt = 0; nt < 8; nt++) {
                mx0 = fmaxf(mx0, fmaxf(sacc[nt][0], sacc[nt][1]));
                mx1 = fmaxf(mx1, fmaxf(sacc[nt][2], sacc[nt][3]));
            }
            mx0 = fmaxf(mx0, __shfl_xor_sync(0xffffffffu, mx0, 1));
            mx0 = fmaxf(mx0, __shfl_xor_sync(0xffffffffu, mx0, 2));
            mx1 = fmaxf(mx1, __shfl_xor_sync(0xffffffffu, mx1, 1));
            mx1 = fmaxf(mx1, __shfl_xor_sync(0xffffffffu, mx1, 2));
            float mn0 = fmaxf(m0, mx0), mn1 = fmaxf(m1, mx1);
            float cr0 = fexp2(m0 - mn0), cr1 = fexp2(m1 - mn1);
            float sum0 = 0.f, sum1 = 0.f;
            #pragma unroll
            for (int nt = 0; nt < 8; nt++) {
                sacc[nt][0] = fexp2(sacc[nt][0] - mn0);
                sacc[nt][1] = fexp2(sacc[nt][1] - mn0);
                sacc[nt][2] = fexp2(sacc[nt][2] - mn1);
                sacc[nt][3] = fexp2(sacc[nt][3] - mn1);
                sum0 += sacc[nt][0] + sacc[nt][1];
                sum1 += sacc[nt][2] + sacc[nt][3];
                oacc[nt][0] *= cr0; oacc[nt][1] *= cr0;
                oacc[nt][2] *= cr1; oacc[nt][3] *= cr1;
            }
            sum0 += __shfl_xor_sync(0xffffffffu, sum0, 1);
            sum0 += __shfl_xor_sync(0xffffffffu, sum0, 2);
            sum1 += __shfl_xor_sync(0xffffffffu, sum1, 1);
            sum1 += __shfl_xor_sync(0xffffffffu, sum1, 2);
            l0 = l0 * cr0 + sum0;
            l1 = l1 * cr1 + sum1;
            m0 = mn0; m1 = mn1;

            #pragma unroll
            for (int j = 0; j < 4; j++) {
                unsigned pa_h[4], pa_l[4];
                #pragma unroll
                for (int half = 0; half < 2; half++) {
                    float x0 = sacc[2*j+half][0], x1 = sacc[2*j+half][1];
                    float x2 = sacc[2*j+half][2], x3 = sacc[2*j+half][3];
                    __nv_bfloat162 hA = __floats2bfloat162_rn(x0, x1);
                    __nv_bfloat162 hB = __floats2bfloat162_rn(x2, x3);
                    float2 fA = __bfloat1622float2(hA), fB = __bfloat1622float2(hB);
                    __nv_bfloat162 lA = __floats2bfloat162_rn(x0 - fA.x, x1 - fA.y);
                    __nv_bfloat162 lB = __floats2bfloat162_rn(x2 - fB.x, x3 - fB.y);
                    pa_h[half*2]     = *(unsigned*)&hA;
                    pa_h[half*2 + 1] = *(unsigned*)&hB;
                    pa_l[half*2]     = *(unsigned*)&lA;
                    pa_l[half*2 + 1] = *(unsigned*)&lB;
                }
                unsigned vb_h[8][2], vb_l[8][2];
                #pragma unroll
                for (int nt2 = 0; nt2 < 4; nt2++) {
                    int k  = j * 16 + (sub & 1) * 8 + li;
                    int ch = nt2 * 2 + (sub >> 1);
                    uint32_t a = stV + k * 128 + ((ch ^ (k & 7)) << 4);
                    unsigned r_[4];
                    LDSM4T(r_, a);
                    vb_h[nt2*2][0] = r_[0]; vb_h[nt2*2][1] = r_[1];
                    vb_h[nt2*2+1][0] = r_[2]; vb_h[nt2*2+1][1] = r_[3];
                    LDSM4T(r_, a + 8192);
                    vb_l[nt2*2][0] = r_[0]; vb_l[nt2*2][1] = r_[1];
                    vb_l[nt2*2+1][0] = r_[2]; vb_l[nt2*2+1][1] = r_[3];
                }
                #pragma unroll
                for (int nt = 0; nt < 8; nt++) {
                    mma16816(oacc[nt], pa_h, vb_h[nt]);
                    mma16816(oacc[nt], pa_h, vb_l[nt]);
                    mma16816(oacc[nt], pa_l, vb_h[nt]);
                }
            }
        }
    }

    float i0 = 1.f / l0, i1 = 1.f / l1;
    size_t row0 = (size_t)(b * CQ + q0 + w * 16 + gid) * 2048;
    size_t row1 = row0 + 8 * 2048;
    #pragma unroll
    for (int nt = 0; nt < 8; nt++) {
        int col = h * 64 + nt * 8 + 2 * tig;
        split_write(s_at_h, s_at_l, row0 + col, oacc[nt][0] * i0, oacc[nt][1] * i0);
        split_write(s_at_h, s_at_l, row1 + col, oacc[nt][2] * i1, oacc[nt][3] * i1);
    }
}

// ---------------- launch ----------------
extern "C" void kernel_launch(void* const* d_in, const int* in_sizes, int n_in,
                              void* d_out, int out_size) {
    const float* hs   = (const float*)d_in[0];
    const float* kb   = (const float*)d_in[1];
    const float* Wq   = (const float*)d_in[2];
    const float* Wk   = (const float*)d_in[3];
    const float* Wv   = (const float*)d_in[4];
    const float* Wo   = (const float*)d_in[5];
    const float* Wqn  = (const float*)d_in[6];
    const float* Wkbk = (const float*)d_in[7];
    const float* Wkbv = (const float*)d_in[8];
    const float* cosT = (const float*)d_in[9];
    const float* sinT = (const float*)d_in[10];
    const int*   pos  = (const int*)d_in[12];
    float* out = (float*)d_out;

    static cudaStream_t s2 = nullptr;
    static cudaEvent_t ev_fork = nullptr, ev_sel = nullptr;
    static int attr_set = 0;
    if (!attr_set) {
        cudaFuncSetAttribute(proj_gemm, cudaFuncAttributeMaxDynamicSharedMemorySize, GSTG * STAGE_BYTES);
        cudaFuncSetAttribute(wo_gemm,   cudaFuncAttributeMaxDynamicSharedMemorySize, GSTG * STAGE_BYTES);
        cudaFuncSetAttribute(attn_tc_kernel, cudaFuncAttributeMaxDynamicSharedMemorySize, ATT_SMEM);
        cudaStreamCreateWithFlags(&s2, cudaStreamNonBlocking);
        cudaEventCreateWithFlags(&ev_fork, cudaEventDisableTiming);
        cudaEventCreateWithFlags(&ev_sel,  cudaEventDisableTiming);
        attr_set = 1;
    }

    const int M = CB * CQ;   // 2048
    const int SMEM = GSTG * STAGE_BYTES;

    // fork: s2 runs Wo split + selection chain in proj_gemm's shadow
    cudaEventRecord(ev_fork, 0);
    cudaStreamWaitEvent(s2, ev_fork, 0);

    // stream 0: bf16 splits (minus Wo) + merged projection GEMM
    splitall_kernel<<<9216, 256>>>(hs, kb, Wq, Wk, Wv, Wqn, Wkbk, Wkbv);
    proj_gemm<<<704, 256, SMEM, 0>>>(pos, cosT, sinT);

    // stream s2: Wo split + factored KB selection (raw inputs only)
    wosplit_kernel<<<2048, 256, 0, s2>>>(Wo);
    hssum_kernel<<<dim3(CB, 16, 8), 128, 0, s2>>>(hs);
    qg_kernel<<<dim3(CB, 64), 512, 0, s2>>>(Wqn);
    qgc_kernel<<<CB, 512, 0, s2>>>();
    vk_kernel<<<dim3(CB, 128), 256, 0, s2>>>(Wkbk);
    scores_kernel<<<(CB * CKB) / 8, 256, 0, s2>>>(kb);
    topk_kernel<<<CB, 32, 0, s2>>>();
    cudaEventRecord(ev_sel, s2);

    // join: attention needs proj outputs (stream 0) + topk (s2)
    cudaStreamWaitEvent(0, ev_sel, 0);
    attn_tc_kernel<<<dim3(CQ / 128, CNH, CB), 256, ATT_SMEM>>>();

    // output projection (single launch, 256 CTAs)
    wo_gemm<<<dim3(CHID/128, M/128), 256, SMEM>>>(out, M, CHID, CHID);
}

// round 15
// speedup vs baseline: 1.0089x; 1.0089x over previous
#include <cuda_runtime.h>
#include <cuda_bf16.h>
#include <math.h>
#include <stdint.h>

// ---------------- problem constants ----------------
constexpr int CB    = 2;
constexpr int CQ    = 1024;
constexpr int CHID  = 2048;
constexpr int CNH   = 32;
constexpr int CNKV  = 8;
constexpr int CHD   = 64;
constexpr int CG    = 4;
constexpr int CKB   = 512;
constexpr int CTOPK = 100;
#define SCALE_L2E 0.18033688f     // 0.125 * log2(e)
#define KB_B2     2.3561430f      // log2(512/100)

// ---------------- selection scratch ----------------
__device__ float g_hssum_part[CB*8*CHID];
__device__ float g_qg_part[CB*64*512];
__device__ float g_qg[CB*512];
__device__ float g_v[CB*CHID];
__device__ float g_scores[CB*CKB];
__device__ int   g_topidx[CB*CTOPK];

// ---------------- bf16 hi/lo buffers ----------------
__device__ __nv_bfloat16 s_hs_h [CB*CQ*CHID],  s_hs_l [CB*CQ*CHID];
__device__ __nv_bfloat16 s_kb_h [CB*CKB*CHID], s_kb_l [CB*CKB*CHID];
__device__ __nv_bfloat16 s_at_h [CB*CQ*CHID],  s_at_l [CB*CQ*CHID];
__device__ __nv_bfloat16 s_wcomb_h[CHID*5120], s_wcomb_l[CHID*5120]; // [K][Wq|Wqn|Wk|Wv]
__device__ __nv_bfloat16 s_wo_h [CHID*CHID],   s_wo_l [CHID*CHID];
__device__ __nv_bfloat16 s_wkb_h[CHID*1024],   s_wkb_l[CHID*1024];   // [K][Wkbk|Wkbv]
// attention operands
__device__ __nv_bfloat16 s_qh  [CB*CQ*CHID],   s_ql  [CB*CQ*CHID];
__device__ __nv_bfloat16 s_kbqh[CB*CQ*CHID],   s_kbql[CB*CQ*CHID];
__device__ __nv_bfloat16 s_kvh [CB*CQ*1024],   s_kvl [CB*CQ*1024];
__device__ __nv_bfloat16 s_kbkvh[CB*CKB*1024], s_kbkvl[CB*CKB*1024];

// ---------------- common PTX helpers ----------------
__device__ __forceinline__ void cp_async16(uint32_t dst, const void* src) {
    asm volatile("cp.async.cg.shared.global [%0], [%1], 16;\n" :: "r"(dst), "l"(src));
}
__device__ __forceinline__ void mma16816(float* c, const unsigned* a, const unsigned* b) {
    asm volatile(
        "mma.sync.aligned.m16n8k16.row.col.f32.bf16.bf16.f32 "
        "{%0,%1,%2,%3}, {%4,%5,%6,%7}, {%8,%9}, {%0,%1,%2,%3};"
        : "+f"(c[0]), "+f"(c[1]), "+f"(c[2]), "+f"(c[3])
        : "r"(a[0]), "r"(a[1]), "r"(a[2]), "r"(a[3]), "r"(b[0]), "r"(b[1]));
}
#define LDSM4(R, addr) asm volatile( \
    "ldmatrix.sync.aligned.m8n8.x4.shared.b16 {%0,%1,%2,%3}, [%4];" \
    : "=r"((R)[0]), "=r"((R)[1]), "=r"((R)[2]), "=r"((R)[3]) : "r"(addr))
#define LDSM4T(R, addr) asm volatile( \
    "ldmatrix.sync.aligned.m8n8.x4.trans.shared.b16 {%0,%1,%2,%3}, [%4];" \
    : "=r"((R)[0]), "=r"((R)[1]), "=r"((R)[2]), "=r"((R)[3]) : "r"(addr))
__device__ __forceinline__ float fexp2(float x) {
    float y; asm("ex2.approx.ftz.f32 %0, %1;" : "=f"(y) : "f"(x)); return y;
}

// ---------------- split helpers ----------------
__device__ __forceinline__ void split8_store(const float* __restrict__ s4base, int i,
                                             __nv_bfloat16* dh, __nv_bfloat16* dl, size_t ob) {
    const float4* s4 = (const float4*)s4base;
    float4 a = s4[i * 2], b4 = s4[i * 2 + 1];
    float vv[8] = {a.x, a.y, a.z, a.w, b4.x, b4.y, b4.z, b4.w};
    __nv_bfloat162 H[4], L[4];
    #pragma unroll
    for (int j = 0; j < 4; j++) {
        __nv_bfloat16 h0 = __float2bfloat16_rn(vv[2*j]);
        __nv_bfloat16 h1 = __float2bfloat16_rn(vv[2*j+1]);
        H[j] = __nv_bfloat162(h0, h1);
        L[j] = __nv_bfloat162(__float2bfloat16_rn(vv[2*j]   - __bfloat162float(h0)),
                              __float2bfloat16_rn(vv[2*j+1] - __bfloat162float(h1)));
    }
    *(uint4*)&dh[ob] = *(uint4*)H;
    *(uint4*)&dl[ob] = *(uint4*)L;
}

// mega split minus Wo: 16 floats/thread, 4608 blocks
__global__ __launch_bounds__(256)
void splitall_kernel(const float* __restrict__ hs, const float* __restrict__ kb,
                     const float* __restrict__ Wq, const float* __restrict__ Wk,
                     const float* __restrict__ Wv,
                     const float* __restrict__ Wqn, const float* __restrict__ Wkbk,
                     const float* __restrict__ Wkbv) {
    int bid = blockIdx.x;
    const float* src; __nv_bfloat16 *dh, *dl;
    int c16pr, ostr, coff;
    if      (bid <  1024) {               src = hs;   dh = s_hs_h;    dl = s_hs_l;    c16pr = 128; ostr = 2048; coff = 0;    }
    else if (bid <  1536) { bid -= 1024;  src = kb;   dh = s_kb_h;    dl = s_kb_l;    c16pr = 128; ostr = 2048; coff = 0;    }
    else if (bid <  2560) { bid -= 1536;  src = Wq;   dh = s_wcomb_h; dl = s_wcomb_l; c16pr = 128; ostr = 5120; coff = 0;    }
    else if (bid <  3584) { bid -= 2560;  src = Wqn;  dh = s_wcomb_h; dl = s_wcomb_l; c16pr = 128; ostr = 5120; coff = 2048; }
    else if (bid <  3840) { bid -= 3584;  src = Wk;   dh = s_wcomb_h; dl = s_wcomb_l; c16pr = 32;  ostr = 5120; coff = 4096; }
    else if (bid <  4096) { bid -= 3840;  src = Wv;   dh = s_wcomb_h; dl = s_wcomb_l; c16pr = 32;  ostr = 5120; coff = 4608; }
    else if (bid <  4352) { bid -= 4096;  src = Wkbk; dh = s_wkb_h;   dl = s_wkb_l;   c16pr = 32;  ostr = 1024; coff = 0;    }
    else                  { bid -= 4352;  src = Wkbv; dh = s_wkb_h;   dl = s_wkb_l;   c16pr = 32;  ostr = 1024; coff = 512;  }

    int i16 = bid * 256 + threadIdx.x;     // float16 index
    int r = i16 / c16pr, c16 = i16 % c16pr;
    size_t ob = (size_t)r * ostr + coff + c16 * 16;
    split8_store(src, i16 * 2,     dh, dl, ob);
    split8_store(src, i16 * 2 + 1, dh, dl, ob + 8);
}

// Wo split (runs on s2 in proj's shadow)
__global__ __launch_bounds__(256)
void wosplit_kernel(const float* __restrict__ Wo) {
    int i = blockIdx.x * 256 + threadIdx.x;
    split8_store(Wo, i, s_wo_h, s_wo_l, (size_t)i * 8);
}

// ---------------- shared GEMM machinery ----------------
constexpr int GBK = 32, GSTG = 3;
constexpr int STAGE_BYTES = 32768;

__device__ __forceinline__ void gemm_issue_stage(
        uint32_t base, int tid,
        const __nv_bfloat16* Ah, const __nv_bfloat16* Al,
        const __nv_bfloat16* Bh, const __nv_bfloat16* Bl,
        int rb, int cb, int k0, int K, int N) {
    #pragma unroll
    for (int it = 0; it < 2; it++) {
        int i = tid + it * 256;
        int r = i >> 2, c = i & 3;
        uint32_t dst = base + r * 64 + (((c ^ ((r >> 1) & 3))) << 4);
        size_t so = (size_t)(rb + r) * K + k0 + c * 8;
        cp_async16(dst,        Ah + so);
        cp_async16(dst + 8192, Al + so);
    }
    #pragma unroll
    for (int it = 0; it < 2; it++) {
        int i = tid + it * 256;
        int r = i >> 4, cn = i & 15;
        uint32_t dst = base + 16384 + r * 256 + (((cn ^ (r & 7))) << 4);
        size_t so = (size_t)(k0 + r) * N + cb + cn * 8;
        cp_async16(dst,        Bh + so);
        cp_async16(dst + 8192, Bl + so);
    }
}

__device__ __forceinline__ void gemm_mainloop(
        uint32_t sb, int tid, int lane, int wm, int wn,
        const __nv_bfloat16* Ah, const __nv_bfloat16* Al,
        const __nv_bfloat16* Bh, const __nv_bfloat16* Bl,
        int rb, int cb, int K, int N, float (&acc)[2][8][4]) {
    const int nk = K / GBK;
    gemm_issue_stage(sb, tid, Ah, Al, Bh, Bl, rb, cb, 0, K, N);
    asm volatile("cp.async.commit_group;\n" ::);
    if (nk > 1) {
        gemm_issue_stage(sb + STAGE_BYTES, tid, Ah, Al, Bh, Bl, rb, cb, GBK, K, N);
    }
    asm volatile("cp.async.commit_group;\n" ::);

    const int sub = lane >> 3, li = lane & 7;
    const int arow_off = ((sub & 1) ? 8 : 0) + li;
    const int akc_off  = (sub >> 1) ? 8 : 0;
    const int bk_off   = ((sub & 1) ? 8 : 0) + li;
    const int bn_off   = (sub >> 1) ? 8 : 0;

    for (int i = 0; i < nk; i++) {
        asm volatile("cp.async.wait_group 1;\n" ::);
        __syncthreads();
        const int st = i % GSTG;
        const uint32_t abase = sb + st * STAGE_BYTES;
        const uint32_t bbase = abase + 16384;
        if (i + 2 < nk)
            gemm_issue_stage(sb + ((i + 2) % GSTG) * STAGE_BYTES, tid,
                             Ah, Al, Bh, Bl, rb, cb, (i + 2) * GBK, K, N);
        asm volatile("cp.async.commit_group;\n" ::);

        #pragma unroll
        for (int kk = 0; kk < GBK; kk += 16) {
            unsigned bh[8][2], bl[8][2];
            #pragma unroll
            for (int np = 0; np < 4; np++) {
                int n0 = wn * 64 + np * 16;
                int k  = kk + bk_off;
                int n  = n0 + bn_off;
                uint32_t addr = bbase + k * 256 + ((((n >> 3) ^ (k & 7))) << 4);
                unsigned r_[4];
                LDSM4T(r_, addr);
                bh[np*2][0] = r_[0]; bh[np*2][1] = r_[1]; bh[np*2+1][0] = r_[2]; bh[np*2+1][1] = r_[3];
                LDSM4T(r_, addr + 8192);
                bl[np*2][0] = r_[0]; bl[np*2][1] = r_[1]; bl[np*2+1][0] = r_[2]; bl[np*2+1][1] = r_[3];
            }
            #pragma unroll
            for (int mt = 0; mt < 2; mt++) {
                int r0 = wm * 32 + mt * 16;
                int row  = r0 + arow_off;
                int kcol = kk + akc_off;
                uint32_t aaddr = abase + row * 64 + ((((kcol >> 3) ^ ((row >> 1) & 3))) << 4);
                unsigned ah[4], al[4];
                LDSM4(ah, aaddr);
                LDSM4(al, aaddr + 8192);
                #pragma unroll
                for (int nt = 0; nt < 8; nt++) {
                    mma16816(acc[mt][nt], ah, bh[nt]);
                    mma16816(acc[mt][nt], ah, bl[nt]);
                    mma16816(acc[mt][nt], al, bh[nt]);
                }
            }
        }
        __syncthreads();
    }
}

__device__ __forceinline__ void rope_acc(float (&a)[8][4], int p0, int p1, int tig,
                                         const float* __restrict__ cosT,
                                         const float* __restrict__ sinT) {
    #pragma unroll
    for (int nt = 0; nt < 4; nt++) {
        const int d0 = nt * 8 + 2 * tig;
        float2 c0l = *(const float2*)&cosT[p0 + d0];
        float2 s0l = *(const float2*)&sinT[p0 + d0];
        float2 c0h = *(const float2*)&cosT[p0 + d0 + 32];
        float2 s0h = *(const float2*)&sinT[p0 + d0 + 32];
        float2 c1l = *(const float2*)&cosT[p1 + d0];
        float2 s1l = *(const float2*)&sinT[p1 + d0];
        float2 c1h = *(const float2*)&cosT[p1 + d0 + 32];
        float2 s1h = *(const float2*)&sinT[p1 + d0 + 32];
        float x1, x2;
        x1 = a[nt][0]; x2 = a[nt+4][0];
        a[nt][0]   = x1 * c0l.x - x2 * s0l.x;
        a[nt+4][0] = x2 * c0h.x + x1 * s0h.x;
        x1 = a[nt][1]; x2 = a[nt+4][1];
        a[nt][1]   = x1 * c0l.y - x2 * s0l.y;
        a[nt+4][1] = x2 * c0h.y + x1 * s0h.y;
        x1 = a[nt][2]; x2 = a[nt+4][2];
        a[nt][2]   = x1 * c1l.x - x2 * s1l.x;
        a[nt+4][2] = x2 * c1h.x + x1 * s1h.x;
        x1 = a[nt][3]; x2 = a[nt+4][3];
        a[nt][3]   = x1 * c1l.y - x2 * s1l.y;
        a[nt+4][3] = x2 * c1h.y + x1 * s1h.y;
    }
}

__device__ __forceinline__ void split_write(__nv_bfloat16* Oh, __nv_bfloat16* Ol,
                                            size_t off, float a, float b) {
    __nv_bfloat162 h = __floats2bfloat162_rn(a, b);
    float2 f = __bfloat1622float2(h);
    __nv_bfloat162 l = __floats2bfloat162_rn(a - f.x, b - f.y);
    *(__nv_bfloat162*)&Oh[off] = h;
    *(__nv_bfloat162*)&Ol[off] = l;
}

// ---------------- merged projection GEMM ----------------
__global__ __launch_bounds__(256)
void proj_gemm(const int* __restrict__ pos,
               const float* __restrict__ cosT, const float* __restrict__ sinT) {
    extern __shared__ char smem[];
    uint32_t sb = (uint32_t)__cvta_generic_to_shared(smem);
    const int tid = threadIdx.x, lane = tid & 31, wid = tid >> 5;
    const int wm = wid >> 1, wn = wid & 1;
    const int gid = lane >> 2, tig = lane & 3;

    const bool iskb = blockIdx.x >= 640;
    int bx, by, N;
    const __nv_bfloat16 *Ah, *Al, *Bh, *Bl;
    if (!iskb) {
        bx = blockIdx.x % 40; by = blockIdx.x / 40; N = 5120;
        Ah = s_hs_h; Al = s_hs_l; Bh = s_wcomb_h; Bl = s_wcomb_l;
    } else {
        int idx = blockIdx.x - 640;
        bx = idx % 8; by = idx / 8; N = 1024;
        Ah = s_kb_h; Al = s_kb_l; Bh = s_wkb_h; Bl = s_wkb_l;
    }
    const int rb = by * 128, cb = bx * 128;

    float acc[2][8][4];
    #pragma unroll
    for (int mt = 0; mt < 2; mt++)
        #pragma unroll
        for (int nt = 0; nt < 8; nt++)
            #pragma unroll
            for (int i = 0; i < 4; i++) acc[mt][nt][i] = 0.f;

    gemm_mainloop(sb, tid, lane, wm, wn, Ah, Al, Bh, Bl, rb, cb, CHID, N, acc);

    const int colbase = cb + wn * 64;
    #pragma unroll
    for (int mt = 0; mt < 2; mt++) {
        const int row0 = rb + wm * 32 + mt * 16 + gid;
        const int row1 = row0 + 8;
        if (iskb) {
            #pragma unroll
            for (int nt = 0; nt < 8; nt++) {
                const int col = colbase + nt * 8 + tig * 2;
                split_write(s_kbkvh, s_kbkvl, (size_t)row0 * 1024 + col, acc[mt][nt][0], acc[mt][nt][1]);
                split_write(s_kbkvh, s_kbkvl, (size_t)row1 * 1024 + col, acc[mt][nt][2], acc[mt][nt][3]);
            }
        } else if (colbase < 2048) {
            rope_acc(acc[mt], pos[row0] * 64, pos[row1] * 64, tig, cosT, sinT);
            #pragma unroll
            for (int nt = 0; nt < 8; nt++) {
                const int col = colbase + nt * 8 + tig * 2;
                split_write(s_qh, s_ql, (size_t)row0 * 2048 + col,
                            acc[mt][nt][0] * SCALE_L2E, acc[mt][nt][1] * SCALE_L2E);
                split_write(s_qh, s_ql, (size_t)row1 * 2048 + col,
                            acc[mt][nt][2] * SCALE_L2E, acc[mt][nt][3] * SCALE_L2E);
            }
        } else if (colbase < 4096) {
            #pragma unroll
            for (int nt = 0; nt < 8; nt++) {
                const int col = colbase - 2048 + nt * 8 + tig * 2;
                split_write(s_kbqh, s_kbql, (size_t)row0 * 2048 + col,
                            acc[mt][nt][0] * SCALE_L2E, acc[mt][nt][1] * SCALE_L2E);
                split_write(s_kbqh, s_kbql, (size_t)row1 * 2048 + col,
                            acc[mt][nt][2] * SCALE_L2E, acc[mt][nt][3] * SCALE_L2E);
            }
        } else {
            if (colbase < 4608)
                rope_acc(acc[mt], pos[row0] * 64, pos[row1] * 64, tig, cosT, sinT);
            #pragma unroll
            for (int nt = 0; nt < 8; nt++) {
                const int col = colbase - 4096 + nt * 8 + tig * 2;
                split_write(s_kvh, s_kvl, (size_t)row0 * 1024 + col, acc[mt][nt][0], acc[mt][nt][1]);
                split_write(s_kvh, s_kvl, (size_t)row1 * 1024 + col, acc[mt][nt][2], acc[mt][nt][3]);
            }
        }
    }
}

// ---------------- output GEMM ----------------
__global__ __launch_bounds__(256)
void wo_gemm(float* __restrict__ Cf, int M, int N, int K) {
    extern __shared__ char smem[];
    uint32_t sb = (uint32_t)__cvta_generic_to_shared(smem);
    const int tid = threadIdx.x, lane = tid & 31, wid = tid >> 5;
    const int wm = wid >> 1, wn = wid & 1;
    const int gid = lane >> 2, tig = lane & 3;
    const int rb = blockIdx.y * 128, cb = blockIdx.x * 128;

    float acc[2][8][4];
    #pragma unroll
    for (int mt = 0; mt < 2; mt++)
        #pragma unroll
        for (int nt = 0; nt < 8; nt++)
            #pragma unroll
            for (int i = 0; i < 4; i++) acc[mt][nt][i] = 0.f;

    gemm_mainloop(sb, tid, lane, wm, wn, s_at_h, s_at_l, s_wo_h, s_wo_l, rb, cb, K, N, acc);

    #pragma unroll
    for (int mt = 0; mt < 2; mt++) {
        int r = rb + wm * 32 + mt * 16;
        #pragma unroll
        for (int nt = 0; nt < 8; nt++) {
            int c = cb + wn * 64 + nt * 8 + tig * 2;
            *(float2*)&Cf[(size_t)(r + gid    ) * N + c] = make_float2(acc[mt][nt][0], acc[mt][nt][1]);
            *(float2*)&Cf[(size_t)(r + gid + 8) * N + c] = make_float2(acc[mt][nt][2], acc[mt][nt][3]);
        }
    }
}

// ---------------- factored KB selection ----------------
__global__ void hssum_kernel(const float* __restrict__ hs) {
    int b = blockIdx.x, c = blockIdx.y * 128 + threadIdx.x, qz = blockIdx.z;
    float s = 0.f;
    const float* p = hs + (size_t)b * CQ * CHID + (size_t)qz * 128 * CHID + c;
    #pragma unroll 8
    for (int q = 0; q < 128; q++) s += p[(size_t)q * CHID];
    g_hssum_part[(b * 8 + qz) * CHID + c] = s;
}

__global__ __launch_bounds__(512) void qg_kernel(const float* __restrict__ Wqn) {
    __shared__ float hsum[CHID];
    int b = blockIdx.x, z = blockIdx.y, c = threadIdx.x;   // c = 0..511
    #pragma unroll
    for (int cc = 0; cc < 4; cc++) {
        int col = cc * 512 + c;
        float s = 0.f;
        #pragma unroll
        for (int qz = 0; qz < 8; qz++) s += g_hssum_part[(b * 8 + qz) * CHID + col];
        hsum[col] = s;
    }
    __syncthreads();
    int kh = c >> 6, d = c & 63;
    float s = 0.f;
    #pragma unroll 4
    for (int j = z * 32; j < z * 32 + 32; j++) {
        const float* wr = Wqn + (size_t)j * CHID + kh * 256 + d;
        s = fmaf(hsum[j], wr[0] + wr[64] + wr[128] + wr[192], s);
    }
    g_qg_part[(b * 64 + z) * 512 + c] = s;
}
__global__ void qgc_kernel() {
    int b = blockIdx.x, c = threadIdx.x;   // 512 threads
    float s = 0.f;
    #pragma unroll
    for (int z = 0; z < 64; z++) s += g_qg_part[(b * 64 + z) * 512 + c];
    g_qg[b * 512 + c] = s;
}

__global__ __launch_bounds__(256) void vk_kernel(const float* __restrict__ Wkbk) {
    __shared__ float qs[512];
    int b = blockIdx.x;
    for (int c = threadIdx.x; c < 512; c += 256) qs[c] = g_qg[b * 512 + c];
    __syncthreads();
    int w = threadIdx.x >> 5, l = threadIdx.x & 31;
    int jbase = blockIdx.y * 16 + w * 2;
    #pragma unroll
    for (int jj = 0; jj < 2; jj++) {
        int j = jbase + jj;
        float s = 0.f;
        #pragma unroll
        for (int c = l; c < 512; c += 32) s = fmaf(Wkbk[(size_t)j * 512 + c], qs[c], s);
        #pragma unroll
        for (int o = 16; o > 0; o >>= 1) s += __shfl_xor_sync(0xffffffffu, s, o);
        if (l == 0) g_v[b * CHID + j] = s;
    }
}

__global__ void scores_kernel(const float* __restrict__ kb) {
    int gw = blockIdx.x * 8 + (threadIdx.x >> 5);
    int l  = threadIdx.x & 31;
    int b  = gw >> 9, n = gw & 511;
    const float* kr = kb + (size_t)(b * CKB + n) * CHID;
    const float* vv = g_v + b * CHID;
    float s = 0.f;
    #pragma unroll 8
    for (int i = l; i < CHID; i += 32) s = fmaf(kr[i], vv[i], s);
    #pragma unroll
    for (int o = 16; o > 0; o >>= 1) s += __shfl_xor_sync(0xffffffffu, s, o);
    if (l == 0) g_scores[b * CKB + n] = s;
}

__global__ void topk_kernel() {
    int b = blockIdx.x, l = threadIdx.x;
    float vreg[16];
    #pragma unroll
    for (int s = 0; s < 16; s++) vreg[s] = g_scores[b * CKB + s * 32 + l];
    for (int t = 0; t < CTOPK; t++) {
        float v = vreg[0]; int idx = l;
        #pragma unroll
        for (int s = 1; s < 16; s++) {
            float x = vreg[s]; int xi = s * 32 + l;
            if (x > v || (x == v && xi < idx)) { v = x; idx = xi; }
        }
        #pragma unroll
        for (int o = 16; o > 0; o >>= 1) {
            float ov = __shfl_xor_sync(0xffffffffu, v, o);
            int   oi = __shfl_xor_sync(0xffffffffu, idx, o);
            if (ov > v || (ov == v && oi < idx)) { v = ov; idx = oi; }
        }
        if (l == 0) g_topidx[b * CTOPK + t] = idx;
        if ((idx & 31) == l) vreg[idx >> 5] = -3.0e38f;
    }
}

// ---------------- tensor-core fused flash attention (64-q tile, 128 threads) ----------------
constexpr int ATT_SMEM = 16384 + 2 * 32768;

__device__ __forceinline__ void attn_load_tile(uint32_t st, int b, int kh, int ph2, int t, int tid) {
    for (int i = tid; i < 512; i += 128) {
        int r = i >> 3, c = i & 7;
        int kg = t * 64 + r;
        const __nv_bfloat16 *H, *L;
        size_t base;
        if (ph2 == 0) {
            int n = (kg < CTOPK) ? g_topidx[b * CTOPK + kg] : 0;
            base = (size_t)(b * CKB + n) * 1024 + kh * 64;
            H = s_kbkvh; L = s_kbkvl;
        } else {
            base = (size_t)(b * CQ + kg) * 1024 + kh * 64;
            H = s_kvh; L = s_kvl;
        }
        uint32_t d = st + r * 128 + ((c ^ (r & 7)) << 4);
        cp_async16(d,         H + base + c * 8);
        cp_async16(d + 8192,  L + base + c * 8);
        cp_async16(d + 16384, H + base + 512 + c * 8);
        cp_async16(d + 24576, L + base + 512 + c * 8);
    }
}

__global__ __launch_bounds__(128) void attn_tc_kernel() {
    extern __shared__ char asmem[];
    uint32_t sq = (uint32_t)__cvta_generic_to_shared(asmem);
    const int tid = threadIdx.x, lane = tid & 31, w = tid >> 5;
    const int gid = lane >> 2, tig = lane & 3;
    const int sub = lane >> 3, li = lane & 7;
    const int qt = (int)(gridDim.x - 1 - blockIdx.x);   // longest-first scheduling
    const int h = blockIdx.y, b = blockIdx.z;
    const int kh = h >> 2;
    const int q0 = qt * 64;

    float m0 = -1e30f, m1 = -1e30f, l0 = 0.f, l1 = 0.f;
    float oacc[8][4];
    #pragma unroll
    for (int nt = 0; nt < 8; nt++)
        #pragma unroll
        for (int c = 0; c < 4; c++) oacc[nt][c] = 0.f;

    for (int ph2 = 0; ph2 < 2; ph2++) {
        __syncthreads();
        const __nv_bfloat16* Qh = ph2 ? s_qh : s_kbqh;
        const __nv_bfloat16* Ql = ph2 ? s_ql : s_kbql;
        for (int i = tid; i < 512; i += 128) {
            int r = i >> 3, c = i & 7;
            uint32_t dst = sq + r * 128 + ((c ^ (r & 7)) << 4);
            size_t src = (size_t)(b * CQ + q0 + r) * 2048 + h * 64 + c * 8;
            cp_async16(dst,        Qh + src);
            cp_async16(dst + 8192, Ql + src);
        }
        const int ntiles = ph2 ? (qt + 1) : 2;
        attn_load_tile(sq + 16384, b, kh, ph2, 0, tid);
        asm volatile("cp.async.commit_group;\n" ::);

        for (int t = 0; t < ntiles; t++) {
            asm volatile("cp.async.wait_group 0;\n" ::);
            __syncthreads();
            if (t + 1 < ntiles) {
                attn_load_tile(sq + 16384 + ((t + 1) & 1) * 32768, b, kh, ph2, t + 1, tid);
                asm volatile("cp.async.commit_group;\n" ::);
            }
            const uint32_t stK = sq + 16384 + (t & 1) * 32768;
            const uint32_t stV = stK + 16384;

            float sacc[8][4];
            #pragma unroll
            for (int nt = 0; nt < 8; nt++)
                #pragma unroll
                for (int c = 0; c < 4; c++) sacc[nt][c] = 0.f;

            #pragma unroll
            for (int k16 = 0; k16 < 4; k16++) {
                int kk = k16 * 16;
                unsigned qa_h[4], qa_l[4];
                {
                    int row = w * 16 + (sub & 1) * 8 + li;
                    int ch  = (kk >> 3) + (sub >> 1);
                    uint32_t a = sq + row * 128 + ((ch ^ (row & 7)) << 4);
                    LDSM4(qa_h, a);
                    LDSM4(qa_l, a + 8192);
                }
                unsigned kb_h[8][2], kb_l[8][2];
                #pragma unroll
                for (int nt2 = 0; nt2 < 4; nt2++) {
                    int n  = nt2 * 16 + (sub >> 1) * 8 + li;
                    int ch = (kk >> 3) + (sub & 1);
                    uint32_t a = stK + n * 128 + ((ch ^ (n & 7)) << 4);
                    unsigned r_[4];
                    LDSM4(r_, a);
                    kb_h[nt2*2][0] = r_[0]; kb_h[nt2*2][1] = r_[1];
                    kb_h[nt2*2+1][0] = r_[2]; kb_h[nt2*2+1][1] = r_[3];
                    LDSM4(r_, a + 8192);
                    kb_l[nt2*2][0] = r_[0]; kb_l[nt2*2][1] = r_[1];
                    kb_l[nt2*2+1][0] = r_[2]; kb_l[nt2*2+1][1] = r_[3];
                }
                #pragma unroll
                for (int nt = 0; nt < 8; nt++) {
                    mma16816(sacc[nt], qa_h, kb_h[nt]);
                    mma16816(sacc[nt], qa_h, kb_l[nt]);
                    mma16816(sacc[nt], qa_l, kb_h[nt]);
                }
            }

            if (ph2 == 0) {
                #pragma unroll
                for (int nt = 0; nt < 8; nt++) {
                    int kg = t * 64 + nt * 8 + 2 * tig;
                    sacc[nt][0] = (kg     < CTOPK) ? sacc[nt][0] + KB_B2 : -1e30f;
                    sacc[nt][1] = (kg + 1 < CTOPK) ? sacc[nt][1] + KB_B2 : -1e30f;
                    sacc[nt][2] = (kg     < CTOPK) ? sacc[nt][2] + KB_B2 : -1e30f;
                    sacc[nt][3] = (kg + 1 < CTOPK) ? sacc[nt][3] + KB_B2 : -1e30f;
                }
            } else if (t == qt) {
                int rq0 = q0 + w * 16 + gid, rq1 = rq0 + 8;
                #pragma unroll
                for (int nt = 0; nt < 8; nt++) {
                    int kg = t * 64 + nt * 8 + 2 * tig;
                    if (kg     > rq0) sacc[nt][0] = -1e30f;
                    if (kg + 1 > rq0) sacc[nt][1] = -1e30f;
                    if (kg     > rq1) sacc[nt][2] = -1e30f;
                    if (kg + 1 > rq1) sacc[nt][3] = -1e30f;
                }
            }

            float mx0 = -1e30f, mx1 = -1e30f;
            #pragma unroll
            for (int nt = 0; nt < 8; nt++) {
                mx0 = fmaxf(mx0, fmaxf(sacc[nt][0], sacc[nt][1]));
                mx1 = fmaxf(mx1, fmaxf(sacc[nt][2], sacc[nt][3]));
            }
            mx0 = fmaxf(mx0, __shfl_xor_sync(0xffffffffu, mx0, 1));
            mx0 = fmaxf(mx0, __shfl_xor_sync(0xffffffffu, mx0, 2));
            mx1 = fmaxf(mx1, __shfl_xor_sync(0xffffffffu, mx1, 1));
            mx1 = fmaxf(mx1, __shfl_xor_sync(0xffffffffu, mx1, 2));
            float mn0 = fmaxf(m0, mx0), mn1 = fmaxf(m1, mx1);
            float cr0 = fexp2(m0 - mn0), cr1 = fexp2(m1 - mn1);
            float sum0 = 0.f, sum1 = 0.f;
            #pragma unroll
            for (int nt = 0; nt < 8; nt++) {
                sacc[nt][0] = fexp2(sacc[nt][0] - mn0);
                sacc[nt][1] = fexp2(sacc[nt][1] - mn0);
                sacc[nt][2] = fexp2(sacc[nt][2] - mn1);
                sacc[nt][3] = fexp2(sacc[nt][3] - mn1);
                sum0 += sacc[nt][0] + sacc[nt][1];
                sum1 += sacc[nt][2] + sacc[nt][3];
                oacc[nt][0] *= cr0; oacc[nt][1] *= cr0;
                oacc[nt][2] *= cr1; oacc[nt][3] *= cr1;
            }
            sum0 += __shfl_xor_sync(0xffffffffu, sum0, 1);
            sum0 += __shfl_xor_sync(0xffffffffu, sum0, 2);
            sum1 += __shfl_xor_sync(0xffffffffu, sum1, 1);
            sum1 += __shfl_xor_sync(0xffffffffu, sum1, 2);
            l0 = l0 * cr0 + sum0;
            l1 = l1 * cr1 + sum1;
            m0 = mn0; m1 = mn1;

            #pragma unroll
            for (int j = 0; j < 4; j++) {
                unsigned pa_h[4], pa_l[4];
                #pragma unroll
                for (int half = 0; half < 2; half++) {
                    float x0 = sacc[2*j+half][0], x1 = sacc[2*j+half][1];
                    float x2 = sacc[2*j+half][2], x3 = sacc[2*j+half][3];
                    __nv_bfloat162 hA = __floats2bfloat162_rn(x0, x1);
                    __nv_bfloat162 hB = __floats2bfloat162_rn(x2, x3);
                    float2 fA = __bfloat1622float2(hA), fB = __bfloat1622float2(hB);
                    __nv_bfloat162 lA = __floats2bfloat162_rn(x0 - fA.x, x1 - fA.y);
                    __nv_bfloat162 lB = __floats2bfloat162_rn(x2 - fB.x, x3 - fB.y);
                    pa_h[half*2]     = *(unsigned*)&hA;
                    pa_h[half*2 + 1] = *(unsigned*)&hB;
                    pa_l[half*2]     = *(unsigned*)&lA;
                    pa_l[half*2 + 1] = *(unsigned*)&lB;
                }
                unsigned vb_h[8][2], vb_l[8][2];
                #pragma unroll
                for (int nt2 = 0; nt2 < 4; nt2++) {
                    int k  = j * 16 + (sub & 1) * 8 + li;
                    int ch = nt2 * 2 + (sub >> 1);
                    uint32_t a = stV + k * 128 + ((ch ^ (k & 7)) << 4);
                    unsigned r_[4];
                    LDSM4T(r_, a);
                    vb_h[nt2*2][0] = r_[0]; vb_h[nt2*2][1] = r_[1];
                    vb_h[nt2*2+1][0] = r_[2]; vb_h[nt2*2+1][1] = r_[3];
                    LDSM4T(r_, a + 8192);
                    vb_l[nt2*2][0] = r_[0]; vb_l[nt2*2][1] = r_[1];
                    vb_l[nt2*2+1][0] = r_[2]; vb_l[nt2*2+1][1] = r_[3];
                }
                #pragma unroll
                for (int nt = 0; nt < 8; nt++) {
                    mma16816(oacc[nt], pa_h, vb_h[nt]);
                    mma16816(oacc[nt], pa_h, vb_l[nt]);
                    mma16816(oacc[nt], pa_l, vb_h[nt]);
                }
            }
        }
    }

    float i0 = 1.f / l0, i1 = 1.f / l1;
    size_t row0 = (size_t)(b * CQ + q0 + w * 16 + gid) * 2048;
    size_t row1 = row0 + 8 * 2048;
    #pragma unroll
    for (int nt = 0; nt < 8; nt++) {
        int col = h * 64 + nt * 8 + 2 * tig;
        split_write(s_at_h, s_at_l, row0 + col, oacc[nt][0] * i0, oacc[nt][1] * i0);
        split_write(s_at_h, s_at_l, row1 + col, oacc[nt][2] * i1, oacc[nt][3] * i1);
    }
}

// ---------------- launch ----------------
extern "C" void kernel_launch(void* const* d_in, const int* in_sizes, int n_in,
                              void* d_out, int out_size) {
    const float* hs   = (const float*)d_in[0];
    const float* kb   = (const float*)d_in[1];
    const float* Wq   = (const float*)d_in[2];
    const float* Wk   = (const float*)d_in[3];
    const float* Wv   = (const float*)d_in[4];
    const float* Wo   = (const float*)d_in[5];
    const float* Wqn  = (const float*)d_in[6];
    const float* Wkbk = (const float*)d_in[7];
    const float* Wkbv = (const float*)d_in[8];
    const float* cosT = (const float*)d_in[9];
    const float* sinT = (const float*)d_in[10];
    const int*   pos  = (const int*)d_in[12];
    float* out = (float*)d_out;

    static cudaStream_t s2 = nullptr;
    static cudaEvent_t ev_fork = nullptr, ev_sel = nullptr;
    static int attr_set = 0;
    if (!attr_set) {
        cudaFuncSetAttribute(proj_gemm, cudaFuncAttributeMaxDynamicSharedMemorySize, GSTG * STAGE_BYTES);
        cudaFuncSetAttribute(wo_gemm,   cudaFuncAttributeMaxDynamicSharedMemorySize, GSTG * STAGE_BYTES);
        cudaFuncSetAttribute(attn_tc_kernel, cudaFuncAttributeMaxDynamicSharedMemorySize, ATT_SMEM);
        cudaStreamCreateWithFlags(&s2, cudaStreamNonBlocking);
        cudaEventCreateWithFlags(&ev_fork, cudaEventDisableTiming);
        cudaEventCreateWithFlags(&ev_sel,  cudaEventDisableTiming);
        attr_set = 1;
    }

    const int M = CB * CQ;   // 2048
    const int SMEM = GSTG * STAGE_BYTES;

    // fork: s2 runs Wo split + selection chain in proj_gemm's shadow
    cudaEventRecord(ev_fork, 0);
    cudaStreamWaitEvent(s2, ev_fork, 0);

    // stream 0: bf16 splits (minus Wo, 16 floats/thread) + merged projection GEMM
    splitall_kernel<<<4608, 256>>>(hs, kb, Wq, Wk, Wv, Wqn, Wkbk, Wkbv);
    proj_gemm<<<704, 256, SMEM, 0>>>(pos, cosT, sinT);

    // stream s2: Wo split + factored KB selection (raw inputs only)
    wosplit_kernel<<<2048, 256, 0, s2>>>(Wo);
    hssum_kernel<<<dim3(CB, 16, 8), 128, 0, s2>>>(hs);
    qg_kernel<<<dim3(CB, 64), 512, 0, s2>>>(Wqn);
    qgc_kernel<<<CB, 512, 0, s2>>>();
    vk_kernel<<<dim3(CB, 128), 256, 0, s2>>>(Wkbk);
    scores_kernel<<<(CB * CKB) / 8, 256, 0, s2>>>(kb);
    topk_kernel<<<CB, 32, 0, s2>>>();
    cudaEventRecord(ev_sel, s2);

    // join: attention needs proj outputs (stream 0) + topk (s2)
    cudaStreamWaitEvent(0, ev_sel, 0);
    attn_tc_kernel<<<dim3(CQ / 64, CNH, CB), 128, ATT_SMEM>>>();

    // output projection (single launch, 256 CTAs)
    wo_gemm<<<dim3(CHID/128, M/128), 256, SMEM>>>(out, M, CHID, CHID);
}

// round 16
// speedup vs baseline: 1.0172x; 1.0082x over previous
#include <cuda_runtime.h>
#include <cuda_bf16.h>
#include <math.h>
#include <stdint.h>

// ---------------- problem constants ----------------
constexpr int CB    = 2;
constexpr int CQ    = 1024;
constexpr int CHID  = 2048;
constexpr int CNH   = 32;
constexpr int CNKV  = 8;
constexpr int CHD   = 64;
constexpr int CG    = 4;
constexpr int CKB   = 512;
constexpr int CTOPK = 100;
#define SCALE_L2E 0.18033688f     // 0.125 * log2(e)
#define KB_B2     2.3561430f      // log2(512/100)

// ---------------- selection scratch ----------------
__device__ float g_hssum_part[CB*8*CHID];
__device__ float g_qg_part[CB*64*512];
__device__ float g_qg[CB*512];
__device__ float g_v[CB*CHID];
__device__ float g_scores[CB*CKB];
__device__ int   g_topidx[CB*CTOPK];

// ---------------- bf16 hi/lo buffers ----------------
__device__ __nv_bfloat16 s_hs_h [CB*CQ*CHID],  s_hs_l [CB*CQ*CHID];
__device__ __nv_bfloat16 s_kb_h [CB*CKB*CHID], s_kb_l [CB*CKB*CHID];
__device__ __nv_bfloat16 s_at_h [CB*CQ*CHID],  s_at_l [CB*CQ*CHID];
__device__ __nv_bfloat16 s_wcomb_h[CHID*5120], s_wcomb_l[CHID*5120]; // [K][Wq|Wqn|Wk|Wv]
__device__ __nv_bfloat16 s_wo_h [CHID*CHID],   s_wo_l [CHID*CHID];
__device__ __nv_bfloat16 s_wkb_h[CHID*1024],   s_wkb_l[CHID*1024];   // [K][Wkbk|Wkbv]
// attention operands
__device__ __nv_bfloat16 s_qh  [CB*CQ*CHID],   s_ql  [CB*CQ*CHID];
__device__ __nv_bfloat16 s_kbqh[CB*CQ*CHID],   s_kbql[CB*CQ*CHID];
__device__ __nv_bfloat16 s_kvh [CB*CQ*1024],   s_kvl [CB*CQ*1024];
__device__ __nv_bfloat16 s_kbkvh[CB*CKB*1024], s_kbkvl[CB*CKB*1024];

// ---------------- common PTX helpers ----------------
__device__ __forceinline__ void cp_async16(uint32_t dst, const void* src) {
    asm volatile("cp.async.cg.shared.global [%0], [%1], 16;\n" :: "r"(dst), "l"(src));
}
__device__ __forceinline__ void mma16816(float* c, const unsigned* a, const unsigned* b) {
    asm volatile(
        "mma.sync.aligned.m16n8k16.row.col.f32.bf16.bf16.f32 "
        "{%0,%1,%2,%3}, {%4,%5,%6,%7}, {%8,%9}, {%0,%1,%2,%3};"
        : "+f"(c[0]), "+f"(c[1]), "+f"(c[2]), "+f"(c[3])
        : "r"(a[0]), "r"(a[1]), "r"(a[2]), "r"(a[3]), "r"(b[0]), "r"(b[1]));
}
#define LDSM4(R, addr) asm volatile( \
    "ldmatrix.sync.aligned.m8n8.x4.shared.b16 {%0,%1,%2,%3}, [%4];" \
    : "=r"((R)[0]), "=r"((R)[1]), "=r"((R)[2]), "=r"((R)[3]) : "r"(addr))
#define LDSM4T(R, addr) asm volatile( \
    "ldmatrix.sync.aligned.m8n8.x4.trans.shared.b16 {%0,%1,%2,%3}, [%4];" \
    : "=r"((R)[0]), "=r"((R)[1]), "=r"((R)[2]), "=r"((R)[3]) : "r"(addr))
__device__ __forceinline__ float fexp2(float x) {
    float y; asm("ex2.approx.ftz.f32 %0, %1;" : "=f"(y) : "f"(x)); return y;
}

// ---------------- split helpers ----------------
__device__ __forceinline__ void split8_store(const float* __restrict__ s4base, int i,
                                             __nv_bfloat16* dh, __nv_bfloat16* dl, size_t ob) {
    const float4* s4 = (const float4*)s4base;
    float4 a = s4[i * 2], b4 = s4[i * 2 + 1];
    float vv[8] = {a.x, a.y, a.z, a.w, b4.x, b4.y, b4.z, b4.w};
    __nv_bfloat162 H[4], L[4];
    #pragma unroll
    for (int j = 0; j < 4; j++) {
        __nv_bfloat16 h0 = __float2bfloat16_rn(vv[2*j]);
        __nv_bfloat16 h1 = __float2bfloat16_rn(vv[2*j+1]);
        H[j] = __nv_bfloat162(h0, h1);
        L[j] = __nv_bfloat162(__float2bfloat16_rn(vv[2*j]   - __bfloat162float(h0)),
                              __float2bfloat16_rn(vv[2*j+1] - __bfloat162float(h1)));
    }
    *(uint4*)&dh[ob] = *(uint4*)H;
    *(uint4*)&dl[ob] = *(uint4*)L;
}

// stream-0 split: hs + Wq + Wqn + Wk + Wv (7168 blocks, 8 floats/thread)
__global__ __launch_bounds__(256)
void splitA_kernel(const float* __restrict__ hs,
                   const float* __restrict__ Wq, const float* __restrict__ Wk,
                   const float* __restrict__ Wv, const float* __restrict__ Wqn) {
    int bid = blockIdx.x;
    const float* src; __nv_bfloat16 *dh, *dl;
    int c8pr, ostr, coff;
    if      (bid <  2048) {               src = hs;  dh = s_hs_h;    dl = s_hs_l;    c8pr = 256; ostr = 2048; coff = 0;    }
    else if (bid <  4096) { bid -= 2048;  src = Wq;  dh = s_wcomb_h; dl = s_wcomb_l; c8pr = 256; ostr = 5120; coff = 0;    }
    else if (bid <  6144) { bid -= 4096;  src = Wqn; dh = s_wcomb_h; dl = s_wcomb_l; c8pr = 256; ostr = 5120; coff = 2048; }
    else if (bid <  6656) { bid -= 6144;  src = Wk;  dh = s_wcomb_h; dl = s_wcomb_l; c8pr = 64;  ostr = 5120; coff = 4096; }
    else                  { bid -= 6656;  src = Wv;  dh = s_wcomb_h; dl = s_wcomb_l; c8pr = 64;  ostr = 5120; coff = 4608; }

    int i = bid * 256 + threadIdx.x;      // float8 index
    int r = i / c8pr, c8 = i % c8pr;
    split8_store(src, i, dh, dl, (size_t)r * ostr + coff + c8 * 8);
}

// stream-s2 split: kb + Wkbk + Wkbv (2048 blocks)
__global__ __launch_bounds__(256)
void splitB_kernel(const float* __restrict__ kb,
                   const float* __restrict__ Wkbk, const float* __restrict__ Wkbv) {
    int bid = blockIdx.x;
    const float* src; __nv_bfloat16 *dh, *dl;
    int c8pr, ostr, coff;
    if      (bid <  1024) {               src = kb;   dh = s_kb_h;  dl = s_kb_l;  c8pr = 256; ostr = 2048; coff = 0;   }
    else if (bid <  1536) { bid -= 1024;  src = Wkbk; dh = s_wkb_h; dl = s_wkb_l; c8pr = 64;  ostr = 1024; coff = 0;   }
    else                  { bid -= 1536;  src = Wkbv; dh = s_wkb_h; dl = s_wkb_l; c8pr = 64;  ostr = 1024; coff = 512; }

    int i = bid * 256 + threadIdx.x;
    int r = i / c8pr, c8 = i % c8pr;
    split8_store(src, i, dh, dl, (size_t)r * ostr + coff + c8 * 8);
}

// Wo split (runs on s2 in proj's shadow)
__global__ __launch_bounds__(256)
void wosplit_kernel(const float* __restrict__ Wo) {
    int i = blockIdx.x * 256 + threadIdx.x;
    split8_store(Wo, i, s_wo_h, s_wo_l, (size_t)i * 8);
}

// ---------------- shared GEMM machinery ----------------
constexpr int GBK = 32, GSTG = 3;
constexpr int STAGE_BYTES = 32768;

__device__ __forceinline__ void gemm_issue_stage(
        uint32_t base, int tid,
        const __nv_bfloat16* Ah, const __nv_bfloat16* Al,
        const __nv_bfloat16* Bh, const __nv_bfloat16* Bl,
        int rb, int cb, int k0, int K, int N) {
    #pragma unroll
    for (int it = 0; it < 2; it++) {
        int i = tid + it * 256;
        int r = i >> 2, c = i & 3;
        uint32_t dst = base + r * 64 + (((c ^ ((r >> 1) & 3))) << 4);
        size_t so = (size_t)(rb + r) * K + k0 + c * 8;
        cp_async16(dst,        Ah + so);
        cp_async16(dst + 8192, Al + so);
    }
    #pragma unroll
    for (int it = 0; it < 2; it++) {
        int i = tid + it * 256;
        int r = i >> 4, cn = i & 15;
        uint32_t dst = base + 16384 + r * 256 + (((cn ^ (r & 7))) << 4);
        size_t so = (size_t)(k0 + r) * N + cb + cn * 8;
        cp_async16(dst,        Bh + so);
        cp_async16(dst + 8192, Bl + so);
    }
}

__device__ __forceinline__ void gemm_mainloop(
        uint32_t sb, int tid, int lane, int wm, int wn,
        const __nv_bfloat16* Ah, const __nv_bfloat16* Al,
        const __nv_bfloat16* Bh, const __nv_bfloat16* Bl,
        int rb, int cb, int K, int N, float (&acc)[2][8][4]) {
    const int nk = K / GBK;
    gemm_issue_stage(sb, tid, Ah, Al, Bh, Bl, rb, cb, 0, K, N);
    asm volatile("cp.async.commit_group;\n" ::);
    if (nk > 1) {
        gemm_issue_stage(sb + STAGE_BYTES, tid, Ah, Al, Bh, Bl, rb, cb, GBK, K, N);
    }
    asm volatile("cp.async.commit_group;\n" ::);

    const int sub = lane >> 3, li = lane & 7;
    const int arow_off = ((sub & 1) ? 8 : 0) + li;
    const int akc_off  = (sub >> 1) ? 8 : 0;
    const int bk_off   = ((sub & 1) ? 8 : 0) + li;
    const int bn_off   = (sub >> 1) ? 8 : 0;

    for (int i = 0; i < nk; i++) {
        asm volatile("cp.async.wait_group 1;\n" ::);
        __syncthreads();
        const int st = i % GSTG;
        const uint32_t abase = sb + st * STAGE_BYTES;
        const uint32_t bbase = abase + 16384;
        if (i + 2 < nk)
            gemm_issue_stage(sb + ((i + 2) % GSTG) * STAGE_BYTES, tid,
                             Ah, Al, Bh, Bl, rb, cb, (i + 2) * GBK, K, N);
        asm volatile("cp.async.commit_group;\n" ::);

        #pragma unroll
        for (int kk = 0; kk < GBK; kk += 16) {
            unsigned bh[8][2], bl[8][2];
            #pragma unroll
            for (int np = 0; np < 4; np++) {
                int n0 = wn * 64 + np * 16;
                int k  = kk + bk_off;
                int n  = n0 + bn_off;
                uint32_t addr = bbase + k * 256 + ((((n >> 3) ^ (k & 7))) << 4);
                unsigned r_[4];
                LDSM4T(r_, addr);
                bh[np*2][0] = r_[0]; bh[np*2][1] = r_[1]; bh[np*2+1][0] = r_[2]; bh[np*2+1][1] = r_[3];
                LDSM4T(r_, addr + 8192);
                bl[np*2][0] = r_[0]; bl[np*2][1] = r_[1]; bl[np*2+1][0] = r_[2]; bl[np*2+1][1] = r_[3];
            }
            #pragma unroll
            for (int mt = 0; mt < 2; mt++) {
                int r0 = wm * 32 + mt * 16;
                int row  = r0 + arow_off;
                int kcol = kk + akc_off;
                uint32_t aaddr = abase + row * 64 + ((((kcol >> 3) ^ ((row >> 1) & 3))) << 4);
                unsigned ah[4], al[4];
                LDSM4(ah, aaddr);
                LDSM4(al, aaddr + 8192);
                #pragma unroll
                for (int nt = 0; nt < 8; nt++) {
                    mma16816(acc[mt][nt], ah, bh[nt]);
                    mma16816(acc[mt][nt], ah, bl[nt]);
                    mma16816(acc[mt][nt], al, bh[nt]);
                }
            }
        }
        __syncthreads();
    }
}

__device__ __forceinline__ void rope_acc(float (&a)[8][4], int p0, int p1, int tig,
                                         const float* __restrict__ cosT,
                                         const float* __restrict__ sinT) {
    #pragma unroll
    for (int nt = 0; nt < 4; nt++) {
        const int d0 = nt * 8 + 2 * tig;
        float2 c0l = *(const float2*)&cosT[p0 + d0];
        float2 s0l = *(const float2*)&sinT[p0 + d0];
        float2 c0h = *(const float2*)&cosT[p0 + d0 + 32];
        float2 s0h = *(const float2*)&sinT[p0 + d0 + 32];
        float2 c1l = *(const float2*)&cosT[p1 + d0];
        float2 s1l = *(const float2*)&sinT[p1 + d0];
        float2 c1h = *(const float2*)&cosT[p1 + d0 + 32];
        float2 s1h = *(const float2*)&sinT[p1 + d0 + 32];
        float x1, x2;
        x1 = a[nt][0]; x2 = a[nt+4][0];
        a[nt][0]   = x1 * c0l.x - x2 * s0l.x;
        a[nt+4][0] = x2 * c0h.x + x1 * s0h.x;
        x1 = a[nt][1]; x2 = a[nt+4][1];
        a[nt][1]   = x1 * c0l.y - x2 * s0l.y;
        a[nt+4][1] = x2 * c0h.y + x1 * s0h.y;
        x1 = a[nt][2]; x2 = a[nt+4][2];
        a[nt][2]   = x1 * c1l.x - x2 * s1l.x;
        a[nt+4][2] = x2 * c1h.x + x1 * s1h.x;
        x1 = a[nt][3]; x2 = a[nt+4][3];
        a[nt][3]   = x1 * c1l.y - x2 * s1l.y;
        a[nt+4][3] = x2 * c1h.y + x1 * s1h.y;
    }
}

__device__ __forceinline__ void split_write(__nv_bfloat16* Oh, __nv_bfloat16* Ol,
                                            size_t off, float a, float b) {
    __nv_bfloat162 h = __floats2bfloat162_rn(a, b);
    float2 f = __bfloat1622float2(h);
    __nv_bfloat162 l = __floats2bfloat162_rn(a - f.x, b - f.y);
    *(__nv_bfloat162*)&Oh[off] = h;
    *(__nv_bfloat162*)&Ol[off] = l;
}

// ---------------- merged projection GEMM ----------------
__global__ __launch_bounds__(256)
void proj_gemm(const int* __restrict__ pos,
               const float* __restrict__ cosT, const float* __restrict__ sinT) {
    extern __shared__ char smem[];
    uint32_t sb = (uint32_t)__cvta_generic_to_shared(smem);
    const int tid = threadIdx.x, lane = tid & 31, wid = tid >> 5;
    const int wm = wid >> 1, wn = wid & 1;
    const int gid = lane >> 2, tig = lane & 3;

    const bool iskb = blockIdx.x >= 640;
    int bx, by, N;
    const __nv_bfloat16 *Ah, *Al, *Bh, *Bl;
    if (!iskb) {
        bx = blockIdx.x % 40; by = blockIdx.x / 40; N = 5120;
        Ah = s_hs_h; Al = s_hs_l; Bh = s_wcomb_h; Bl = s_wcomb_l;
    } else {
        int idx = blockIdx.x - 640;
        bx = idx % 8; by = idx / 8; N = 1024;
        Ah = s_kb_h; Al = s_kb_l; Bh = s_wkb_h; Bl = s_wkb_l;
    }
    const int rb = by * 128, cb = bx * 128;

    float acc[2][8][4];
    #pragma unroll
    for (int mt = 0; mt < 2; mt++)
        #pragma unroll
        for (int nt = 0; nt < 8; nt++)
            #pragma unroll
            for (int i = 0; i < 4; i++) acc[mt][nt][i] = 0.f;

    gemm_mainloop(sb, tid, lane, wm, wn, Ah, Al, Bh, Bl, rb, cb, CHID, N, acc);

    const int colbase = cb + wn * 64;
    #pragma unroll
    for (int mt = 0; mt < 2; mt++) {
        const int row0 = rb + wm * 32 + mt * 16 + gid;
        const int row1 = row0 + 8;
        if (iskb) {
            #pragma unroll
            for (int nt = 0; nt < 8; nt++) {
                const int col = colbase + nt * 8 + tig * 2;
                split_write(s_kbkvh, s_kbkvl, (size_t)row0 * 1024 + col, acc[mt][nt][0], acc[mt][nt][1]);
                split_write(s_kbkvh, s_kbkvl, (size_t)row1 * 1024 + col, acc[mt][nt][2], acc[mt][nt][3]);
            }
        } else if (colbase < 2048) {
            rope_acc(acc[mt], pos[row0] * 64, pos[row1] * 64, tig, cosT, sinT);
            #pragma unroll
            for (int nt = 0; nt < 8; nt++) {
                const int col = colbase + nt * 8 + tig * 2;
                split_write(s_qh, s_ql, (size_t)row0 * 2048 + col,
                            acc[mt][nt][0] * SCALE_L2E, acc[mt][nt][1] * SCALE_L2E);
                split_write(s_qh, s_ql, (size_t)row1 * 2048 + col,
                            acc[mt][nt][2] * SCALE_L2E, acc[mt][nt][3] * SCALE_L2E);
            }
        } else if (colbase < 4096) {
            #pragma unroll
            for (int nt = 0; nt < 8; nt++) {
                const int col = colbase - 2048 + nt * 8 + tig * 2;
                split_write(s_kbqh, s_kbql, (size_t)row0 * 2048 + col,
                            acc[mt][nt][0] * SCALE_L2E, acc[mt][nt][1] * SCALE_L2E);
                split_write(s_kbqh, s_kbql, (size_t)row1 * 2048 + col,
                            acc[mt][nt][2] * SCALE_L2E, acc[mt][nt][3] * SCALE_L2E);
            }
        } else {
            if (colbase < 4608)
                rope_acc(acc[mt], pos[row0] * 64, pos[row1] * 64, tig, cosT, sinT);
            #pragma unroll
            for (int nt = 0; nt < 8; nt++) {
                const int col = colbase - 4096 + nt * 8 + tig * 2;
                split_write(s_kvh, s_kvl, (size_t)row0 * 1024 + col, acc[mt][nt][0], acc[mt][nt][1]);
                split_write(s_kvh, s_kvl, (size_t)row1 * 1024 + col, acc[mt][nt][2], acc[mt][nt][3]);
            }
        }
    }
}

// ---------------- output GEMM ----------------
__global__ __launch_bounds__(256)
void wo_gemm(float* __restrict__ Cf, int M, int N, int K) {
    extern __shared__ char smem[];
    uint32_t sb = (uint32_t)__cvta_generic_to_shared(smem);
    const int tid = threadIdx.x, lane = tid & 31, wid = tid >> 5;
    const int wm = wid >> 1, wn = wid & 1;
    const int gid = lane >> 2, tig = lane & 3;
    const int rb = blockIdx.y * 128, cb = blockIdx.x * 128;

    float acc[2][8][4];
    #pragma unroll
    for (int mt = 0; mt < 2; mt++)
        #pragma unroll
        for (int nt = 0; nt < 8; nt++)
            #pragma unroll
            for (int i = 0; i < 4; i++) acc[mt][nt][i] = 0.f;

    gemm_mainloop(sb, tid, lane, wm, wn, s_at_h, s_at_l, s_wo_h, s_wo_l, rb, cb, K, N, acc);

    #pragma unroll
    for (int mt = 0; mt < 2; mt++) {
        int r = rb + wm * 32 + mt * 16;
        #pragma unroll
        for (int nt = 0; nt < 8; nt++) {
            int c = cb + wn * 64 + nt * 8 + tig * 2;
            *(float2*)&Cf[(size_t)(r + gid    ) * N + c] = make_float2(acc[mt][nt][0], acc[mt][nt][1]);
            *(float2*)&Cf[(size_t)(r + gid + 8) * N + c] = make_float2(acc[mt][nt][2], acc[mt][nt][3]);
        }
    }
}

// ---------------- factored KB selection ----------------
__global__ void hssum_kernel(const float* __restrict__ hs) {
    int b = blockIdx.x, c = blockIdx.y * 128 + threadIdx.x, qz = blockIdx.z;
    float s = 0.f;
    const float* p = hs + (size_t)b * CQ * CHID + (size_t)qz * 128 * CHID + c;
    #pragma unroll 8
    for (int q = 0; q < 128; q++) s += p[(size_t)q * CHID];
    g_hssum_part[(b * 8 + qz) * CHID + c] = s;
}

__global__ __launch_bounds__(512) void qg_kernel(const float* __restrict__ Wqn) {
    __shared__ float hsum[CHID];
    int b = blockIdx.x, z = blockIdx.y, c = threadIdx.x;   // c = 0..511
    #pragma unroll
    for (int cc = 0; cc < 4; cc++) {
        int col = cc * 512 + c;
        float s = 0.f;
        #pragma unroll
        for (int qz = 0; qz < 8; qz++) s += g_hssum_part[(b * 8 + qz) * CHID + col];
        hsum[col] = s;
    }
    __syncthreads();
    int kh = c >> 6, d = c & 63;
    float s = 0.f;
    #pragma unroll 4
    for (int j = z * 32; j < z * 32 + 32; j++) {
        const float* wr = Wqn + (size_t)j * CHID + kh * 256 + d;
        s = fmaf(hsum[j], wr[0] + wr[64] + wr[128] + wr[192], s);
    }
    g_qg_part[(b * 64 + z) * 512 + c] = s;
}
__global__ void qgc_kernel() {
    int b = blockIdx.x, c = threadIdx.x;   // 512 threads
    float s = 0.f;
    #pragma unroll
    for (int z = 0; z < 64; z++) s += g_qg_part[(b * 64 + z) * 512 + c];
    g_qg[b * 512 + c] = s;
}

__global__ __launch_bounds__(256) void vk_kernel(const float* __restrict__ Wkbk) {
    __shared__ float qs[512];
    int b = blockIdx.x;
    for (int c = threadIdx.x; c < 512; c += 256) qs[c] = g_qg[b * 512 + c];
    __syncthreads();
    int w = threadIdx.x >> 5, l = threadIdx.x & 31;
    int jbase = blockIdx.y * 16 + w * 2;
    #pragma unroll
    for (int jj = 0; jj < 2; jj++) {
        int j = jbase + jj;
        float s = 0.f;
        #pragma unroll
        for (int c = l; c < 512; c += 32) s = fmaf(Wkbk[(size_t)j * 512 + c], qs[c], s);
        #pragma unroll
        for (int o = 16; o > 0; o >>= 1) s += __shfl_xor_sync(0xffffffffu, s, o);
        if (l == 0) g_v[b * CHID + j] = s;
    }
}

__global__ void scores_kernel(const float* __restrict__ kb) {
    int gw = blockIdx.x * 8 + (threadIdx.x >> 5);
    int l  = threadIdx.x & 31;
    int b  = gw >> 9, n = gw & 511;
    const float* kr = kb + (size_t)(b * CKB + n) * CHID;
    const float* vv = g_v + b * CHID;
    float s = 0.f;
    #pragma unroll 8
    for (int i = l; i < CHID; i += 32) s = fmaf(kr[i], vv[i], s);
    #pragma unroll
    for (int o = 16; o > 0; o >>= 1) s += __shfl_xor_sync(0xffffffffu, s, o);
    if (l == 0) g_scores[b * CKB + n] = s;
}

__global__ void topk_kernel() {
    int b = blockIdx.x, l = threadIdx.x;
    float vreg[16];
    #pragma unroll
    for (int s = 0; s < 16; s++) vreg[s] = g_scores[b * CKB + s * 32 + l];
    for (int t = 0; t < CTOPK; t++) {
        float v = vreg[0]; int idx = l;
        #pragma unroll
        for (int s = 1; s < 16; s++) {
            float x = vreg[s]; int xi = s * 32 + l;
            if (x > v || (x == v && xi < idx)) { v = x; idx = xi; }
        }
        #pragma unroll
        for (int o = 16; o > 0; o >>= 1) {
            float ov = __shfl_xor_sync(0xffffffffu, v, o);
            int   oi = __shfl_xor_sync(0xffffffffu, idx, o);
            if (ov > v || (ov == v && oi < idx)) { v = ov; idx = oi; }
        }
        if (l == 0) g_topidx[b * CTOPK + t] = idx;
        if ((idx & 31) == l) vreg[idx >> 5] = -3.0e38f;
    }
}

// ---------------- tensor-core fused flash attention (64-q tile, 128 threads) ----------------
constexpr int ATT_SMEM = 16384 + 2 * 32768;

__device__ __forceinline__ void attn_load_tile(uint32_t st, int b, int kh, int ph2, int t, int tid) {
    for (int i = tid; i < 512; i += 128) {
        int r = i >> 3, c = i & 7;
        int kg = t * 64 + r;
        const __nv_bfloat16 *H, *L;
        size_t base;
        if (ph2 == 0) {
            int n = (kg < CTOPK) ? g_topidx[b * CTOPK + kg] : 0;
            base = (size_t)(b * CKB + n) * 1024 + kh * 64;
            H = s_kbkvh; L = s_kbkvl;
        } else {
            base = (size_t)(b * CQ + kg) * 1024 + kh * 64;
            H = s_kvh; L = s_kvl;
        }
        uint32_t d = st + r * 128 + ((c ^ (r & 7)) << 4);
        cp_async16(d,         H + base + c * 8);
        cp_async16(d + 8192,  L + base + c * 8);
        cp_async16(d + 16384, H + base + 512 + c * 8);
        cp_async16(d + 24576, L + base + 512 + c * 8);
    }
}

__global__ __launch_bounds__(128) void attn_tc_kernel() {
    extern __shared__ char asmem[];
    uint32_t sq = (uint32_t)__cvta_generic_to_shared(asmem);
    const int tid = threadIdx.x, lane = tid & 31, w = tid >> 5;
    const int gid = lane >> 2, tig = lane & 3;
    const int sub = lane >> 3, li = lane & 7;
    const int qt = (int)(gridDim.x - 1 - blockIdx.x);   // longest-first scheduling
    const int h = blockIdx.y, b = blockIdx.z;
    const int kh = h >> 2;
    const int q0 = qt * 64;

    float m0 = -1e30f, m1 = -1e30f, l0 = 0.f, l1 = 0.f;
    float oacc[8][4];
    #pragma unroll
    for (int nt = 0; nt < 8; nt++)
        #pragma unroll
        for (int c = 0; c < 4; c++) oacc[nt][c] = 0.f;

    for (int ph2 = 0; ph2 < 2; ph2++) {
        __syncthreads();
        const __nv_bfloat16* Qh = ph2 ? s_qh : s_kbqh;
        const __nv_bfloat16* Ql = ph2 ? s_ql : s_kbql;
        for (int i = tid; i < 512; i += 128) {
            int r = i >> 3, c = i & 7;
            uint32_t dst = sq + r * 128 + ((c ^ (r & 7)) << 4);
            size_t src = (size_t)(b * CQ + q0 + r) * 2048 + h * 64 + c * 8;
            cp_async16(dst,        Qh + src);
            cp_async16(dst + 8192, Ql + src);
        }
        const int ntiles = ph2 ? (qt + 1) : 2;
        attn_load_tile(sq + 16384, b, kh, ph2, 0, tid);
        asm volatile("cp.async.commit_group;\n" ::);

        for (int t = 0; t < ntiles; t++) {
            asm volatile("cp.async.wait_group 0;\n" ::);
            __syncthreads();
            if (t + 1 < ntiles) {
                attn_load_tile(sq + 16384 + ((t + 1) & 1) * 32768, b, kh, ph2, t + 1, tid);
                asm volatile("cp.async.commit_group;\n" ::);
            }
            const uint32_t stK = sq + 16384 + (t & 1) * 32768;
            const uint32_t stV = stK + 16384;

            float sacc[8][4];
            #pragma unroll
            for (int nt = 0; nt < 8; nt++)
                #pragma unroll
                for (int c = 0; c < 4; c++) sacc[nt][c] = 0.f;

            #pragma unroll
            for (int k16 = 0; k16 < 4; k16++) {
                int kk = k16 * 16;
                unsigned qa_h[4], qa_l[4];
                {
                    int row = w * 16 + (sub & 1) * 8 + li;
                    int ch  = (kk >> 3) + (sub >> 1);
                    uint32_t a = sq + row * 128 + ((ch ^ (row & 7)) << 4);
                    LDSM4(qa_h, a);
                    LDSM4(qa_l, a + 8192);
                }
                unsigned kb_h[8][2], kb_l[8][2];
                #pragma unroll
                for (int nt2 = 0; nt2 < 4; nt2++) {
                    int n  = nt2 * 16 + (sub >> 1) * 8 + li;
                    int ch = (kk >> 3) + (sub & 1);
                    uint32_t a = stK + n * 128 + ((ch ^ (n & 7)) << 4);
                    unsigned r_[4];
                    LDSM4(r_, a);
                    kb_h[nt2*2][0] = r_[0]; kb_h[nt2*2][1] = r_[1];
                    kb_h[nt2*2+1][0] = r_[2]; kb_h[nt2*2+1][1] = r_[3];
                    LDSM4(r_, a + 8192);
                    kb_l[nt2*2][0] = r_[0]; kb_l[nt2*2][1] = r_[1];
                    kb_l[nt2*2+1][0] = r_[2]; kb_l[nt2*2+1][1] = r_[3];
                }
                #pragma unroll
                for (int nt = 0; nt < 8; nt++) {
                    mma16816(sacc[nt], qa_h, kb_h[nt]);
                    mma16816(sacc[nt], qa_h, kb_l[nt]);
                    mma16816(sacc[nt], qa_l, kb_h[nt]);
                }
            }

            if (ph2 == 0) {
                #pragma unroll
                for (int nt = 0; nt < 8; nt++) {
                    int kg = t * 64 + nt * 8 + 2 * tig;
                    sacc[nt][0] = (kg     < CTOPK) ? sacc[nt][0] + KB_B2 : -1e30f;
                    sacc[nt][1] = (kg + 1 < CTOPK) ? sacc[nt][1] + KB_B2 : -1e30f;
                    sacc[nt][2] = (kg     < CTOPK) ? sacc[nt][2] + KB_B2 : -1e30f;
                    sacc[nt][3] = (kg + 1 < CTOPK) ? sacc[nt][3] + KB_B2 : -1e30f;
                }
            } else if (t == qt) {
                int rq0 = q0 + w * 16 + gid, rq1 = rq0 + 8;
                #pragma unroll
                for (int nt = 0; nt < 8; nt++) {
                    int kg = t * 64 + nt * 8 + 2 * tig;
                    if (kg     > rq0) sacc[nt][0] = -1e30f;
                    if (kg + 1 > rq0) sacc[nt][1] = -1e30f;
                    if (kg     > rq1) sacc[nt][2] = -1e30f;
                    if (kg + 1 > rq1) sacc[nt][3] = -1e30f;
                }
            }

            float mx0 = -1e30f, mx1 = -1e30f;
            #pragma unroll
            for (int nt = 0; nt < 8; nt++) {
                mx0 = fmaxf(mx0, fmaxf(sacc[nt][0], sacc[nt][1]));
                mx1 = fmaxf(mx1, fmaxf(sacc[nt][2], sacc[nt][3]));
            }
            mx0 = fmaxf(mx0, __shfl_xor_sync(0xffffffffu, mx0, 1));
            mx0 = fmaxf(mx0, __shfl_xor_sync(0xffffffffu, mx0, 2));
            mx1 = fmaxf(mx1, __shfl_xor_sync(0xffffffffu, mx1, 1));
            mx1 = fmaxf(mx1, __shfl_xor_sync(0xffffffffu, mx1, 2));
            float mn0 = fmaxf(m0, mx0), mn1 = fmaxf(m1, mx1);
            float cr0 = fexp2(m0 - mn0), cr1 = fexp2(m1 - mn1);
            float sum0 = 0.f, sum1 = 0.f;
            #pragma unroll
            for (int nt = 0; nt < 8; nt++) {
                sacc[nt][0] = fexp2(sacc[nt][0] - mn0);
                sacc[nt][1] = fexp2(sacc[nt][1] - mn0);
                sacc[nt][2] = fexp2(sacc[nt][2] - mn1);
                sacc[nt][3] = fexp2(sacc[nt][3] - mn1);
                sum0 += sacc[nt][0] + sacc[nt][1];
                sum1 += sacc[nt][2] + sacc[nt][3];
                oacc[nt][0] *= cr0; oacc[nt][1] *= cr0;
                oacc[nt][2] *= cr1; oacc[nt][3] *= cr1;
            }
            sum0 += __shfl_xor_sync(0xffffffffu, sum0, 1);
            sum0 += __shfl_xor_sync(0xffffffffu, sum0, 2);
            sum1 += __shfl_xor_sync(0xffffffffu, sum1, 1);
            sum1 += __shfl_xor_sync(0xffffffffu, sum1, 2);
            l0 = l0 * cr0 + sum0;
            l1 = l1 * cr1 + sum1;
            m0 = mn0; m1 = mn1;

            #pragma unroll
            for (int j = 0; j < 4; j++) {
                unsigned pa_h[4], pa_l[4];
                #pragma unroll
                for (int half = 0; half < 2; half++) {
                    float x0 = sacc[2*j+half][0], x1 = sacc[2*j+half][1];
                    float x2 = sacc[2*j+half][2], x3 = sacc[2*j+half][3];
                    __nv_bfloat162 hA = __floats2bfloat162_rn(x0, x1);
                    __nv_bfloat162 hB = __floats2bfloat162_rn(x2, x3);
                    float2 fA = __bfloat1622float2(hA), fB = __bfloat1622float2(hB);
                    __nv_bfloat162 lA = __floats2bfloat162_rn(x0 - fA.x, x1 - fA.y);
                    __nv_bfloat162 lB = __floats2bfloat162_rn(x2 - fB.x, x3 - fB.y);
                    pa_h[half*2]     = *(unsigned*)&hA;
                    pa_h[half*2 + 1] = *(unsigned*)&hB;
                    pa_l[half*2]     = *(unsigned*)&lA;
                    pa_l[half*2 + 1] = *(unsigned*)&lB;
                }
                unsigned vb_h[8][2], vb_l[8][2];
                #pragma unroll
                for (int nt2 = 0; nt2 < 4; nt2++) {
                    int k  = j * 16 + (sub & 1) * 8 + li;
                    int ch = nt2 * 2 + (sub >> 1);
                    uint32_t a = stV + k * 128 + ((ch ^ (k & 7)) << 4);
                    unsigned r_[4];
                    LDSM4T(r_, a);
                    vb_h[nt2*2][0] = r_[0]; vb_h[nt2*2][1] = r_[1];
                    vb_h[nt2*2+1][0] = r_[2]; vb_h[nt2*2+1][1] = r_[3];
                    LDSM4T(r_, a + 8192);
                    vb_l[nt2*2][0] = r_[0]; vb_l[nt2*2][1] = r_[1];
                    vb_l[nt2*2+1][0] = r_[2]; vb_l[nt2*2+1][1] = r_[3];
                }
                #pragma unroll
                for (int nt = 0; nt < 8; nt++) {
                    mma16816(oacc[nt], pa_h, vb_h[nt]);
                    mma16816(oacc[nt], pa_h, vb_l[nt]);
                    mma16816(oacc[nt], pa_l, vb_h[nt]);
                }
            }
        }
    }

    float i0 = 1.f / l0, i1 = 1.f / l1;
    size_t row0 = (size_t)(b * CQ + q0 + w * 16 + gid) * 2048;
    size_t row1 = row0 + 8 * 2048;
    #pragma unroll
    for (int nt = 0; nt < 8; nt++) {
        int col = h * 64 + nt * 8 + 2 * tig;
        split_write(s_at_h, s_at_l, row0 + col, oacc[nt][0] * i0, oacc[nt][1] * i0);
        split_write(s_at_h, s_at_l, row1 + col, oacc[nt][2] * i1, oacc[nt][3] * i1);
    }
}

// ---------------- launch ----------------
extern "C" void kernel_launch(void* const* d_in, const int* in_sizes, int n_in,
                              void* d_out, int out_size) {
    const float* hs   = (const float*)d_in[0];
    const float* kb   = (const float*)d_in[1];
    const float* Wq   = (const float*)d_in[2];
    const float* Wk   = (const float*)d_in[3];
    const float* Wv   = (const float*)d_in[4];
    const float* Wo   = (const float*)d_in[5];
    const float* Wqn  = (const float*)d_in[6];
    const float* Wkbk = (const float*)d_in[7];
    const float* Wkbv = (const float*)d_in[8];
    const float* cosT = (const float*)d_in[9];
    const float* sinT = (const float*)d_in[10];
    const int*   pos  = (const int*)d_in[12];
    float* out = (float*)d_out;

    static cudaStream_t s2 = nullptr;
    static cudaEvent_t ev_fork = nullptr, ev_sel = nullptr, ev_bsplit = nullptr;
    static int attr_set = 0;
    if (!attr_set) {
        cudaFuncSetAttribute(proj_gemm, cudaFuncAttributeMaxDynamicSharedMemorySize, GSTG * STAGE_BYTES);
        cudaFuncSetAttribute(wo_gemm,   cudaFuncAttributeMaxDynamicSharedMemorySize, GSTG * STAGE_BYTES);
        cudaFuncSetAttribute(attn_tc_kernel, cudaFuncAttributeMaxDynamicSharedMemorySize, ATT_SMEM);
        cudaStreamCreateWithFlags(&s2, cudaStreamNonBlocking);
        cudaEventCreateWithFlags(&ev_fork,   cudaEventDisableTiming);
        cudaEventCreateWithFlags(&ev_sel,    cudaEventDisableTiming);
        cudaEventCreateWithFlags(&ev_bsplit, cudaEventDisableTiming);
        attr_set = 1;
    }

    const int M = CB * CQ;   // 2048
    const int SMEM = GSTG * STAGE_BYTES;

    // fork
    cudaEventRecord(ev_fork, 0);
    cudaStreamWaitEvent(s2, ev_fork, 0);

    // stream 0: main splits (hs + Wq/Wqn/Wk/Wv)
    splitA_kernel<<<7168, 256>>>(hs, Wq, Wk, Wv, Wqn);

    // stream s2: kb/wkb splits (gating proj) run concurrently with splitA
    splitB_kernel<<<2048, 256, 0, s2>>>(kb, Wkbk, Wkbv);
    cudaEventRecord(ev_bsplit, s2);

    // proj waits for both streams' splits
    cudaStreamWaitEvent(0, ev_bsplit, 0);
    proj_gemm<<<704, 256, SMEM, 0>>>(pos, cosT, sinT);

    // stream s2 (in proj's shadow): Wo split + factored KB selection
    wosplit_kernel<<<2048, 256, 0, s2>>>(Wo);
    hssum_kernel<<<dim3(CB, 16, 8), 128, 0, s2>>>(hs);
    qg_kernel<<<dim3(CB, 64), 512, 0, s2>>>(Wqn);
    qgc_kernel<<<CB, 512, 0, s2>>>();
    vk_kernel<<<dim3(CB, 128), 256, 0, s2>>>(Wkbk);
    scores_kernel<<<(CB * CKB) / 8, 256, 0, s2>>>(kb);
    topk_kernel<<<CB, 32, 0, s2>>>();
    cudaEventRecord(ev_sel, s2);

    // join: attention needs proj outputs (stream 0) + topk (s2)
    cudaStreamWaitEvent(0, ev_sel, 0);
    attn_tc_kernel<<<dim3(CQ / 64, CNH, CB), 128, ATT_SMEM>>>();

    // output projection (single launch, 256 CTAs)
    wo_gemm<<<dim3(CHID/128, M/128), 256, SMEM>>>(out, M, CHID, CHID);
}

// round 17
// speedup vs baseline: 1.0227x; 1.0054x over previous
#include <cuda_runtime.h>
#include <cuda_bf16.h>
#include <math.h>
#include <stdint.h>

// ---------------- problem constants ----------------
constexpr int CB    = 2;
constexpr int CQ    = 1024;
constexpr int CHID  = 2048;
constexpr int CNH   = 32;
constexpr int CNKV  = 8;
constexpr int CHD   = 64;
constexpr int CG    = 4;
constexpr int CKB   = 512;
constexpr int CTOPK = 100;
#define SCALE_L2E 0.18033688f     // 0.125 * log2(e)
#define KB_B2     2.3561430f      // log2(512/100)

// ---------------- selection scratch ----------------
__device__ float g_hssum_part[CB*8*CHID];
__device__ float g_qg_part[CB*64*512];
__device__ float g_qg[CB*512];
__device__ float g_v[CB*CHID];
__device__ float g_scores[CB*CKB];
__device__ int   g_topidx[CB*CTOPK];

// ---------------- bf16 hi/lo buffers ----------------
__device__ __nv_bfloat16 s_hs_h [CB*CQ*CHID],  s_hs_l [CB*CQ*CHID];
__device__ __nv_bfloat16 s_kb_h [CB*CKB*CHID], s_kb_l [CB*CKB*CHID];
__device__ __nv_bfloat16 s_at_h [CB*CQ*CHID],  s_at_l [CB*CQ*CHID];
__device__ __nv_bfloat16 s_wcomb_h[CHID*5120], s_wcomb_l[CHID*5120]; // [K][Wq|Wqn|Wk|Wv]
__device__ __nv_bfloat16 s_wo_h [CHID*CHID],   s_wo_l [CHID*CHID];
__device__ __nv_bfloat16 s_wkb_h[CHID*1024],   s_wkb_l[CHID*1024];   // [K][Wkbk|Wkbv]
// attention operands
__device__ __nv_bfloat16 s_qh  [CB*CQ*CHID],   s_ql  [CB*CQ*CHID];
__device__ __nv_bfloat16 s_kbqh[CB*CQ*CHID],   s_kbql[CB*CQ*CHID];
__device__ __nv_bfloat16 s_kvh [CB*CQ*1024],   s_kvl [CB*CQ*1024];
__device__ __nv_bfloat16 s_kbkvh[CB*CKB*1024], s_kbkvl[CB*CKB*1024];

// ---------------- common PTX helpers ----------------
__device__ __forceinline__ void cp_async16(uint32_t dst, const void* src) {
    asm volatile("cp.async.cg.shared.global [%0], [%1], 16;\n" :: "r"(dst), "l"(src));
}
__device__ __forceinline__ void mma16816(float* c, const unsigned* a, const unsigned* b) {
    asm volatile(
        "mma.sync.aligned.m16n8k16.row.col.f32.bf16.bf16.f32 "
        "{%0,%1,%2,%3}, {%4,%5,%6,%7}, {%8,%9}, {%0,%1,%2,%3};"
        : "+f"(c[0]), "+f"(c[1]), "+f"(c[2]), "+f"(c[3])
        : "r"(a[0]), "r"(a[1]), "r"(a[2]), "r"(a[3]), "r"(b[0]), "r"(b[1]));
}
#define LDSM4(R, addr) asm volatile( \
    "ldmatrix.sync.aligned.m8n8.x4.shared.b16 {%0,%1,%2,%3}, [%4];" \
    : "=r"((R)[0]), "=r"((R)[1]), "=r"((R)[2]), "=r"((R)[3]) : "r"(addr))
#define LDSM4T(R, addr) asm volatile( \
    "ldmatrix.sync.aligned.m8n8.x4.trans.shared.b16 {%0,%1,%2,%3}, [%4];" \
    : "=r"((R)[0]), "=r"((R)[1]), "=r"((R)[2]), "=r"((R)[3]) : "r"(addr))
__device__ __forceinline__ float fexp2(float x) {
    float y; asm("ex2.approx.ftz.f32 %0, %1;" : "=f"(y) : "f"(x)); return y;
}

// ---------------- split helpers ----------------
__device__ __forceinline__ void split8_store(const float* __restrict__ s4base, int i,
                                             __nv_bfloat16* dh, __nv_bfloat16* dl, size_t ob) {
    const float4* s4 = (const float4*)s4base;
    float4 a = s4[i * 2], b4 = s4[i * 2 + 1];
    float vv[8] = {a.x, a.y, a.z, a.w, b4.x, b4.y, b4.z, b4.w};
    __nv_bfloat162 H[4], L[4];
    #pragma unroll
    for (int j = 0; j < 4; j++) {
        __nv_bfloat16 h0 = __float2bfloat16_rn(vv[2*j]);
        __nv_bfloat16 h1 = __float2bfloat16_rn(vv[2*j+1]);
        H[j] = __nv_bfloat162(h0, h1);
        L[j] = __nv_bfloat162(__float2bfloat16_rn(vv[2*j]   - __bfloat162float(h0)),
                              __float2bfloat16_rn(vv[2*j+1] - __bfloat162float(h1)));
    }
    *(uint4*)&dh[ob] = *(uint4*)H;
    *(uint4*)&dl[ob] = *(uint4*)L;
}

// stream-0 split: hs + Wq + Wqn + Wk + Wv (7168 blocks, 8 floats/thread)
__global__ __launch_bounds__(256)
void splitA_kernel(const float* __restrict__ hs,
                   const float* __restrict__ Wq, const float* __restrict__ Wk,
                   const float* __restrict__ Wv, const float* __restrict__ Wqn) {
    int bid = blockIdx.x;
    const float* src; __nv_bfloat16 *dh, *dl;
    int c8pr, ostr, coff;
    if      (bid <  2048) {               src = hs;  dh = s_hs_h;    dl = s_hs_l;    c8pr = 256; ostr = 2048; coff = 0;    }
    else if (bid <  4096) { bid -= 2048;  src = Wq;  dh = s_wcomb_h; dl = s_wcomb_l; c8pr = 256; ostr = 5120; coff = 0;    }
    else if (bid <  6144) { bid -= 4096;  src = Wqn; dh = s_wcomb_h; dl = s_wcomb_l; c8pr = 256; ostr = 5120; coff = 2048; }
    else if (bid <  6656) { bid -= 6144;  src = Wk;  dh = s_wcomb_h; dl = s_wcomb_l; c8pr = 64;  ostr = 5120; coff = 4096; }
    else                  { bid -= 6656;  src = Wv;  dh = s_wcomb_h; dl = s_wcomb_l; c8pr = 64;  ostr = 5120; coff = 4608; }

    int i = bid * 256 + threadIdx.x;      // float8 index
    int r = i / c8pr, c8 = i % c8pr;
    split8_store(src, i, dh, dl, (size_t)r * ostr + coff + c8 * 8);
}

// stream-s2 split: kb + Wkbk + Wkbv (2048 blocks)
__global__ __launch_bounds__(256)
void splitB_kernel(const float* __restrict__ kb,
                   const float* __restrict__ Wkbk, const float* __restrict__ Wkbv) {
    int bid = blockIdx.x;
    const float* src; __nv_bfloat16 *dh, *dl;
    int c8pr, ostr, coff;
    if      (bid <  1024) {               src = kb;   dh = s_kb_h;  dl = s_kb_l;  c8pr = 256; ostr = 2048; coff = 0;   }
    else if (bid <  1536) { bid -= 1024;  src = Wkbk; dh = s_wkb_h; dl = s_wkb_l; c8pr = 64;  ostr = 1024; coff = 0;   }
    else                  { bid -= 1536;  src = Wkbv; dh = s_wkb_h; dl = s_wkb_l; c8pr = 64;  ostr = 1024; coff = 512; }

    int i = bid * 256 + threadIdx.x;
    int r = i / c8pr, c8 = i % c8pr;
    split8_store(src, i, dh, dl, (size_t)r * ostr + coff + c8 * 8);
}

// Wo split (runs on s2 in proj's shadow)
__global__ __launch_bounds__(256)
void wosplit_kernel(const float* __restrict__ Wo) {
    int i = blockIdx.x * 256 + threadIdx.x;
    split8_store(Wo, i, s_wo_h, s_wo_l, (size_t)i * 8);
}

// ---------------- shared GEMM machinery ----------------
constexpr int GBK = 32, GSTG = 3;
constexpr int STAGE_BYTES = 32768;

__device__ __forceinline__ void gemm_issue_stage(
        uint32_t base, int tid,
        const __nv_bfloat16* Ah, const __nv_bfloat16* Al,
        const __nv_bfloat16* Bh, const __nv_bfloat16* Bl,
        int rb, int cb, int k0, int K, int N) {
    #pragma unroll
    for (int it = 0; it < 2; it++) {
        int i = tid + it * 256;
        int r = i >> 2, c = i & 3;
        uint32_t dst = base + r * 64 + (((c ^ ((r >> 1) & 3))) << 4);
        size_t so = (size_t)(rb + r) * K + k0 + c * 8;
        cp_async16(dst,        Ah + so);
        cp_async16(dst + 8192, Al + so);
    }
    #pragma unroll
    for (int it = 0; it < 2; it++) {
        int i = tid + it * 256;
        int r = i >> 4, cn = i & 15;
        uint32_t dst = base + 16384 + r * 256 + (((cn ^ (r & 7))) << 4);
        size_t so = (size_t)(k0 + r) * N + cb + cn * 8;
        cp_async16(dst,        Bh + so);
        cp_async16(dst + 8192, Bl + so);
    }
}

__device__ __forceinline__ void gemm_mainloop(
        uint32_t sb, int tid, int lane, int wm, int wn,
        const __nv_bfloat16* Ah, const __nv_bfloat16* Al,
        const __nv_bfloat16* Bh, const __nv_bfloat16* Bl,
        int rb, int cb, int K, int N, float (&acc)[2][8][4]) {
    const int nk = K / GBK;
    gemm_issue_stage(sb, tid, Ah, Al, Bh, Bl, rb, cb, 0, K, N);
    asm volatile("cp.async.commit_group;\n" ::);
    if (nk > 1) {
        gemm_issue_stage(sb + STAGE_BYTES, tid, Ah, Al, Bh, Bl, rb, cb, GBK, K, N);
    }
    asm volatile("cp.async.commit_group;\n" ::);

    const int sub = lane >> 3, li = lane & 7;
    const int arow_off = ((sub & 1) ? 8 : 0) + li;
    const int akc_off  = (sub >> 1) ? 8 : 0;
    const int bk_off   = ((sub & 1) ? 8 : 0) + li;
    const int bn_off   = (sub >> 1) ? 8 : 0;

    for (int i = 0; i < nk; i++) {
        asm volatile("cp.async.wait_group 1;\n" ::);
        __syncthreads();
        const int st = i % GSTG;
        const uint32_t abase = sb + st * STAGE_BYTES;
        const uint32_t bbase = abase + 16384;
        if (i + 2 < nk)
            gemm_issue_stage(sb + ((i + 2) % GSTG) * STAGE_BYTES, tid,
                             Ah, Al, Bh, Bl, rb, cb, (i + 2) * GBK, K, N);
        asm volatile("cp.async.commit_group;\n" ::);

        #pragma unroll
        for (int kk = 0; kk < GBK; kk += 16) {
            unsigned bh[8][2], bl[8][2];
            #pragma unroll
            for (int np = 0; np < 4; np++) {
                int n0 = wn * 64 + np * 16;
                int k  = kk + bk_off;
                int n  = n0 + bn_off;
                uint32_t addr = bbase + k * 256 + ((((n >> 3) ^ (k & 7))) << 4);
                unsigned r_[4];
                LDSM4T(r_, addr);
                bh[np*2][0] = r_[0]; bh[np*2][1] = r_[1]; bh[np*2+1][0] = r_[2]; bh[np*2+1][1] = r_[3];
                LDSM4T(r_, addr + 8192);
                bl[np*2][0] = r_[0]; bl[np*2][1] = r_[1]; bl[np*2+1][0] = r_[2]; bl[np*2+1][1] = r_[3];
            }
            #pragma unroll
            for (int mt = 0; mt < 2; mt++) {
                int r0 = wm * 32 + mt * 16;
                int row  = r0 + arow_off;
                int kcol = kk + akc_off;
                uint32_t aaddr = abase + row * 64 + ((((kcol >> 3) ^ ((row >> 1) & 3))) << 4);
                unsigned ah[4], al[4];
                LDSM4(ah, aaddr);
                LDSM4(al, aaddr + 8192);
                #pragma unroll
                for (int nt = 0; nt < 8; nt++) {
                    mma16816(acc[mt][nt], ah, bh[nt]);
                    mma16816(acc[mt][nt], ah, bl[nt]);
                    mma16816(acc[mt][nt], al, bh[nt]);
                }
            }
        }
        __syncthreads();
    }
}

__device__ __forceinline__ void rope_acc(float (&a)[8][4], int p0, int p1, int tig,
                                         const float* __restrict__ cosT,
                                         const float* __restrict__ sinT) {
    #pragma unroll
    for (int nt = 0; nt < 4; nt++) {
        const int d0 = nt * 8 + 2 * tig;
        float2 c0l = *(const float2*)&cosT[p0 + d0];
        float2 s0l = *(const float2*)&sinT[p0 + d0];
        float2 c0h = *(const float2*)&cosT[p0 + d0 + 32];
        float2 s0h = *(const float2*)&sinT[p0 + d0 + 32];
        float2 c1l = *(const float2*)&cosT[p1 + d0];
        float2 s1l = *(const float2*)&sinT[p1 + d0];
        float2 c1h = *(const float2*)&cosT[p1 + d0 + 32];
        float2 s1h = *(const float2*)&sinT[p1 + d0 + 32];
        float x1, x2;
        x1 = a[nt][0]; x2 = a[nt+4][0];
        a[nt][0]   = x1 * c0l.x - x2 * s0l.x;
        a[nt+4][0] = x2 * c0h.x + x1 * s0h.x;
        x1 = a[nt][1]; x2 = a[nt+4][1];
        a[nt][1]   = x1 * c0l.y - x2 * s0l.y;
        a[nt+4][1] = x2 * c0h.y + x1 * s0h.y;
        x1 = a[nt][2]; x2 = a[nt+4][2];
        a[nt][2]   = x1 * c1l.x - x2 * s1l.x;
        a[nt+4][2] = x2 * c1h.x + x1 * s1h.x;
        x1 = a[nt][3]; x2 = a[nt+4][3];
        a[nt][3]   = x1 * c1l.y - x2 * s1l.y;
        a[nt+4][3] = x2 * c1h.y + x1 * s1h.y;
    }
}

__device__ __forceinline__ void split_write(__nv_bfloat16* Oh, __nv_bfloat16* Ol,
                                            size_t off, float a, float b) {
    __nv_bfloat162 h = __floats2bfloat162_rn(a, b);
    float2 f = __bfloat1622float2(h);
    __nv_bfloat162 l = __floats2bfloat162_rn(a - f.x, b - f.y);
    *(__nv_bfloat162*)&Oh[off] = h;
    *(__nv_bfloat162*)&Ol[off] = l;
}

// ---------------- merged projection GEMM ----------------
__global__ __launch_bounds__(256)
void proj_gemm(const int* __restrict__ pos,
               const float* __restrict__ cosT, const float* __restrict__ sinT) {
    extern __shared__ char smem[];
    uint32_t sb = (uint32_t)__cvta_generic_to_shared(smem);
    const int tid = threadIdx.x, lane = tid & 31, wid = tid >> 5;
    const int wm = wid >> 1, wn = wid & 1;
    const int gid = lane >> 2, tig = lane & 3;

    const bool iskb = blockIdx.x >= 640;
    int bx, by, N;
    const __nv_bfloat16 *Ah, *Al, *Bh, *Bl;
    if (!iskb) {
        bx = blockIdx.x % 40; by = blockIdx.x / 40; N = 5120;
        Ah = s_hs_h; Al = s_hs_l; Bh = s_wcomb_h; Bl = s_wcomb_l;
    } else {
        int idx = blockIdx.x - 640;
        bx = idx % 8; by = idx / 8; N = 1024;
        Ah = s_kb_h; Al = s_kb_l; Bh = s_wkb_h; Bl = s_wkb_l;
    }
    const int rb = by * 128, cb = bx * 128;

    float acc[2][8][4];
    #pragma unroll
    for (int mt = 0; mt < 2; mt++)
        #pragma unroll
        for (int nt = 0; nt < 8; nt++)
            #pragma unroll
            for (int i = 0; i < 4; i++) acc[mt][nt][i] = 0.f;

    gemm_mainloop(sb, tid, lane, wm, wn, Ah, Al, Bh, Bl, rb, cb, CHID, N, acc);

    const int colbase = cb + wn * 64;
    #pragma unroll
    for (int mt = 0; mt < 2; mt++) {
        const int row0 = rb + wm * 32 + mt * 16 + gid;
        const int row1 = row0 + 8;
        if (iskb) {
            #pragma unroll
            for (int nt = 0; nt < 8; nt++) {
                const int col = colbase + nt * 8 + tig * 2;
                split_write(s_kbkvh, s_kbkvl, (size_t)row0 * 1024 + col, acc[mt][nt][0], acc[mt][nt][1]);
                split_write(s_kbkvh, s_kbkvl, (size_t)row1 * 1024 + col, acc[mt][nt][2], acc[mt][nt][3]);
            }
        } else if (colbase < 2048) {
            rope_acc(acc[mt], pos[row0] * 64, pos[row1] * 64, tig, cosT, sinT);
            #pragma unroll
            for (int nt = 0; nt < 8; nt++) {
                const int col = colbase + nt * 8 + tig * 2;
                split_write(s_qh, s_ql, (size_t)row0 * 2048 + col,
                            acc[mt][nt][0] * SCALE_L2E, acc[mt][nt][1] * SCALE_L2E);
                split_write(s_qh, s_ql, (size_t)row1 * 2048 + col,
                            acc[mt][nt][2] * SCALE_L2E, acc[mt][nt][3] * SCALE_L2E);
            }
        } else if (colbase < 4096) {
            #pragma unroll
            for (int nt = 0; nt < 8; nt++) {
                const int col = colbase - 2048 + nt * 8 + tig * 2;
                split_write(s_kbqh, s_kbql, (size_t)row0 * 2048 + col,
                            acc[mt][nt][0] * SCALE_L2E, acc[mt][nt][1] * SCALE_L2E);
                split_write(s_kbqh, s_kbql, (size_t)row1 * 2048 + col,
                            acc[mt][nt][2] * SCALE_L2E, acc[mt][nt][3] * SCALE_L2E);
            }
        } else {
            if (colbase < 4608)
                rope_acc(acc[mt], pos[row0] * 64, pos[row1] * 64, tig, cosT, sinT);
            #pragma unroll
            for (int nt = 0; nt < 8; nt++) {
                const int col = colbase - 4096 + nt * 8 + tig * 2;
                split_write(s_kvh, s_kvl, (size_t)row0 * 1024 + col, acc[mt][nt][0], acc[mt][nt][1]);
                split_write(s_kvh, s_kvl, (size_t)row1 * 1024 + col, acc[mt][nt][2], acc[mt][nt][3]);
            }
        }
    }
}

// ---------------- output GEMM ----------------
__global__ __launch_bounds__(256)
void wo_gemm(float* __restrict__ Cf, int M, int N, int K) {
    extern __shared__ char smem[];
    uint32_t sb = (uint32_t)__cvta_generic_to_shared(smem);
    const int tid = threadIdx.x, lane = tid & 31, wid = tid >> 5;
    const int wm = wid >> 1, wn = wid & 1;
    const int gid = lane >> 2, tig = lane & 3;
    const int rb = blockIdx.y * 128, cb = blockIdx.x * 128;

    float acc[2][8][4];
    #pragma unroll
    for (int mt = 0; mt < 2; mt++)
        #pragma unroll
        for (int nt = 0; nt < 8; nt++)
            #pragma unroll
            for (int i = 0; i < 4; i++) acc[mt][nt][i] = 0.f;

    gemm_mainloop(sb, tid, lane, wm, wn, s_at_h, s_at_l, s_wo_h, s_wo_l, rb, cb, K, N, acc);

    #pragma unroll
    for (int mt = 0; mt < 2; mt++) {
        int r = rb + wm * 32 + mt * 16;
        #pragma unroll
        for (int nt = 0; nt < 8; nt++) {
            int c = cb + wn * 64 + nt * 8 + tig * 2;
            *(float2*)&Cf[(size_t)(r + gid    ) * N + c] = make_float2(acc[mt][nt][0], acc[mt][nt][1]);
            *(float2*)&Cf[(size_t)(r + gid + 8) * N + c] = make_float2(acc[mt][nt][2], acc[mt][nt][3]);
        }
    }
}

// ---------------- factored KB selection ----------------
__global__ void hssum_kernel(const float* __restrict__ hs) {
    int b = blockIdx.x, c = blockIdx.y * 128 + threadIdx.x, qz = blockIdx.z;
    float s = 0.f;
    const float* p = hs + (size_t)b * CQ * CHID + (size_t)qz * 128 * CHID + c;
    #pragma unroll 8
    for (int q = 0; q < 128; q++) s += p[(size_t)q * CHID];
    g_hssum_part[(b * 8 + qz) * CHID + c] = s;
}

__global__ __launch_bounds__(512) void qg_kernel(const float* __restrict__ Wqn) {
    __shared__ float hsum[CHID];
    int b = blockIdx.x, z = blockIdx.y, c = threadIdx.x;   // c = 0..511
    #pragma unroll
    for (int cc = 0; cc < 4; cc++) {
        int col = cc * 512 + c;
        float s = 0.f;
        #pragma unroll
        for (int qz = 0; qz < 8; qz++) s += g_hssum_part[(b * 8 + qz) * CHID + col];
        hsum[col] = s;
    }
    __syncthreads();
    int kh = c >> 6, d = c & 63;
    float s = 0.f;
    #pragma unroll 4
    for (int j = z * 32; j < z * 32 + 32; j++) {
        const float* wr = Wqn + (size_t)j * CHID + kh * 256 + d;
        s = fmaf(hsum[j], wr[0] + wr[64] + wr[128] + wr[192], s);
    }
    g_qg_part[(b * 64 + z) * 512 + c] = s;
}
__global__ void qgc_kernel() {
    int b = blockIdx.x, c = threadIdx.x;   // 512 threads
    float s = 0.f;
    #pragma unroll
    for (int z = 0; z < 64; z++) s += g_qg_part[(b * 64 + z) * 512 + c];
    g_qg[b * 512 + c] = s;
}

__global__ __launch_bounds__(256) void vk_kernel(const float* __restrict__ Wkbk) {
    __shared__ float qs[512];
    int b = blockIdx.x;
    for (int c = threadIdx.x; c < 512; c += 256) qs[c] = g_qg[b * 512 + c];
    __syncthreads();
    int w = threadIdx.x >> 5, l = threadIdx.x & 31;
    int jbase = blockIdx.y * 16 + w * 2;
    #pragma unroll
    for (int jj = 0; jj < 2; jj++) {
        int j = jbase + jj;
        float s = 0.f;
        #pragma unroll
        for (int c = l; c < 512; c += 32) s = fmaf(Wkbk[(size_t)j * 512 + c], qs[c], s);
        #pragma unroll
        for (int o = 16; o > 0; o >>= 1) s += __shfl_xor_sync(0xffffffffu, s, o);
        if (l == 0) g_v[b * CHID + j] = s;
    }
}

__global__ void scores_kernel(const float* __restrict__ kb) {
    int gw = blockIdx.x * 8 + (threadIdx.x >> 5);
    int l  = threadIdx.x & 31;
    int b  = gw >> 9, n = gw & 511;
    const float* kr = kb + (size_t)(b * CKB + n) * CHID;
    const float* vv = g_v + b * CHID;
    float s = 0.f;
    #pragma unroll 8
    for (int i = l; i < CHID; i += 32) s = fmaf(kr[i], vv[i], s);
    #pragma unroll
    for (int o = 16; o > 0; o >>= 1) s += __shfl_xor_sync(0xffffffffu, s, o);
    if (l == 0) g_scores[b * CKB + n] = s;
}

__global__ void topk_kernel() {
    int b = blockIdx.x, l = threadIdx.x;
    float vreg[16];
    #pragma unroll
    for (int s = 0; s < 16; s++) vreg[s] = g_scores[b * CKB + s * 32 + l];
    for (int t = 0; t < CTOPK; t++) {
        float v = vreg[0]; int idx = l;
        #pragma unroll
        for (int s = 1; s < 16; s++) {
            float x = vreg[s]; int xi = s * 32 + l;
            if (x > v || (x == v && xi < idx)) { v = x; idx = xi; }
        }
        #pragma unroll
        for (int o = 16; o > 0; o >>= 1) {
            float ov = __shfl_xor_sync(0xffffffffu, v, o);
            int   oi = __shfl_xor_sync(0xffffffffu, idx, o);
            if (ov > v || (ov == v && oi < idx)) { v = ov; idx = oi; }
        }
        if (l == 0) g_topidx[b * CTOPK + t] = idx;
        if ((idx & 31) == l) vreg[idx >> 5] = -3.0e38f;
    }
}

// ---------------- tensor-core fused flash attention (Q in registers, 64 KB smem, 3 CTAs/SM) ----------------
constexpr int ATT_SMEM = 2 * 32768;   // 2 stages x { Kh 8K | Kl 8K | Vh 8K | Vl 8K }

__device__ __forceinline__ void attn_load_tile(uint32_t st, int b, int kh, int ph2, int t, int tid) {
    for (int i = tid; i < 512; i += 128) {
        int r = i >> 3, c = i & 7;
        int kg = t * 64 + r;
        const __nv_bfloat16 *H, *L;
        size_t base;
        if (ph2 == 0) {
            int n = (kg < CTOPK) ? g_topidx[b * CTOPK + kg] : 0;
            base = (size_t)(b * CKB + n) * 1024 + kh * 64;
            H = s_kbkvh; L = s_kbkvl;
        } else {
            base = (size_t)(b * CQ + kg) * 1024 + kh * 64;
            H = s_kvh; L = s_kvl;
        }
        uint32_t d = st + r * 128 + ((c ^ (r & 7)) << 4);
        cp_async16(d,         H + base + c * 8);
        cp_async16(d + 8192,  L + base + c * 8);
        cp_async16(d + 16384, H + base + 512 + c * 8);
        cp_async16(d + 24576, L + base + 512 + c * 8);
    }
}

__global__ __launch_bounds__(128, 3) void attn_tc_kernel() {
    extern __shared__ char asmem[];
    uint32_t sq = (uint32_t)__cvta_generic_to_shared(asmem);
    const int tid = threadIdx.x, lane = tid & 31, w = tid >> 5;
    const int gid = lane >> 2, tig = lane & 3;
    const int sub = lane >> 3, li = lane & 7;
    const int qt = (int)(gridDim.x - 1 - blockIdx.x);   // longest-first scheduling
    const int h = blockIdx.y, b = blockIdx.z;
    const int kh = h >> 2;
    const int q0 = qt * 64;

    float m0 = -1e30f, m1 = -1e30f, l0 = 0.f, l1 = 0.f;
    float oacc[8][4];
    #pragma unroll
    for (int nt = 0; nt < 8; nt++)
        #pragma unroll
        for (int c = 0; c < 4; c++) oacc[nt][c] = 0.f;

    for (int ph2 = 0; ph2 < 2; ph2++) {
        __syncthreads();   // prior phase fully drained; stage buffers free
        // ---- stage Q through stage-0 buffer, then hoist to registers ----
        const __nv_bfloat16* Qh = ph2 ? s_qh : s_kbqh;
        const __nv_bfloat16* Ql = ph2 ? s_ql : s_kbql;
        for (int i = tid; i < 512; i += 128) {
            int r = i >> 3, c = i & 7;
            uint32_t dst = sq + r * 128 + ((c ^ (r & 7)) << 4);
            size_t src = (size_t)(b * CQ + q0 + r) * 2048 + h * 64 + c * 8;
            cp_async16(dst,        Qh + src);
            cp_async16(dst + 8192, Ql + src);
        }
        asm volatile("cp.async.commit_group;\n" ::);
        asm volatile("cp.async.wait_group 0;\n" ::);
        __syncthreads();

        unsigned qa_h[4][4], qa_l[4][4];
        #pragma unroll
        for (int k16 = 0; k16 < 4; k16++) {
            int kk = k16 * 16;
            int row = w * 16 + (sub & 1) * 8 + li;
            int ch  = (kk >> 3) + (sub >> 1);
            uint32_t a = sq + row * 128 + ((ch ^ (row & 7)) << 4);
            LDSM4(qa_h[k16], a);
            LDSM4(qa_l[k16], a + 8192);
        }
        __syncthreads();   // all warps done reading Q before tile-0 overwrites stage 0

        const int ntiles = ph2 ? (qt + 1) : 2;
        attn_load_tile(sq, b, kh, ph2, 0, tid);
        asm volatile("cp.async.commit_group;\n" ::);

        for (int t = 0; t < ntiles; t++) {
            asm volatile("cp.async.wait_group 0;\n" ::);
            __syncthreads();
            if (t + 1 < ntiles) {
                attn_load_tile(sq + ((t + 1) & 1) * 32768, b, kh, ph2, t + 1, tid);
                asm volatile("cp.async.commit_group;\n" ::);
            }
            const uint32_t stK = sq + (t & 1) * 32768;
            const uint32_t stV = stK + 16384;

            float sacc[8][4];
            #pragma unroll
            for (int nt = 0; nt < 8; nt++)
                #pragma unroll
                for (int c = 0; c < 4; c++) sacc[nt][c] = 0.f;

            #pragma unroll
            for (int k16 = 0; k16 < 4; k16++) {
                int kk = k16 * 16;
                unsigned kb_h[8][2], kb_l[8][2];
                #pragma unroll
                for (int nt2 = 0; nt2 < 4; nt2++) {
                    int n  = nt2 * 16 + (sub >> 1) * 8 + li;
                    int ch = (kk >> 3) + (sub & 1);
                    uint32_t a = stK + n * 128 + ((ch ^ (n & 7)) << 4);
                    unsigned r_[4];
                    LDSM4(r_, a);
                    kb_h[nt2*2][0] = r_[0]; kb_h[nt2*2][1] = r_[1];
                    kb_h[nt2*2+1][0] = r_[2]; kb_h[nt2*2+1][1] = r_[3];
                    LDSM4(r_, a + 8192);
                    kb_l[nt2*2][0] = r_[0]; kb_l[nt2*2][1] = r_[1];
                    kb_l[nt2*2+1][0] = r_[2]; kb_l[nt2*2+1][1] = r_[3];
                }
                #pragma unroll
                for (int nt = 0; nt < 8; nt++) {
                    mma16816(sacc[nt], qa_h[k16], kb_h[nt]);
                    mma16816(sacc[nt], qa_h[k16], kb_l[nt]);
                    mma16816(sacc[nt], qa_l[k16], kb_h[nt]);
                }
            }

            if (ph2 == 0) {
                #pragma unroll
                for (int nt = 0; nt < 8; nt++) {
                    int kg = t * 64 + nt * 8 + 2 * tig;
                    sacc[nt][0] = (kg     < CTOPK) ? sacc[nt][0] + KB_B2 : -1e30f;
                    sacc[nt][1] = (kg + 1 < CTOPK) ? sacc[nt][1] + KB_B2 : -1e30f;
                    sacc[nt][2] = (kg     < CTOPK) ? sacc[nt][2] + KB_B2 : -1e30f;
                    sacc[nt][3] = (kg + 1 < CTOPK) ? sacc[nt][3] + KB_B2 : -1e30f;
                }
            } else if (t == qt) {
                int rq0 = q0 + w * 16 + gid, rq1 = rq0 + 8;
                #pragma unroll
                for (int nt = 0; nt < 8; nt++) {
                    int kg = t * 64 + nt * 8 + 2 * tig;
                    if (kg     > rq0) sacc[nt][0] = -1e30f;
                    if (kg + 1 > rq0) sacc[nt][1] = -1e30f;
                    if (kg     > rq1) sacc[nt][2] = -1e30f;
                    if (kg + 1 > rq1) sacc[nt][3] = -1e30f;
                }
            }

            float mx0 = -1e30f, mx1 = -1e30f;
            #pragma unroll
            for (int nt = 0; nt < 8; nt++) {
                mx0 = fmaxf(mx0, fmaxf(sacc[nt][0], sacc[nt][1]));
                mx1 = fmaxf(mx1, fmaxf(sacc[nt][2], sacc[nt][3]));
            }
            mx0 = fmaxf(mx0, __shfl_xor_sync(0xffffffffu, mx0, 1));
            mx0 = fmaxf(mx0, __shfl_xor_sync(0xffffffffu, mx0, 2));
            mx1 = fmaxf(mx1, __shfl_xor_sync(0xffffffffu, mx1, 1));
            mx1 = fmaxf(mx1, __shfl_xor_sync(0xffffffffu, mx1, 2));
            float mn0 = fmaxf(m0, mx0), mn1 = fmaxf(m1, mx1);
            float cr0 = fexp2(m0 - mn0), cr1 = fexp2(m1 - mn1);
            float sum0 = 0.f, sum1 = 0.f;
            #pragma unroll
            for (int nt = 0; nt < 8; nt++) {
                sacc[nt][0] = fexp2(sacc[nt][0] - mn0);
                sacc[nt][1] = fexp2(sacc[nt][1] - mn0);
                sacc[nt][2] = fexp2(sacc[nt][2] - mn1);
                sacc[nt][3] = fexp2(sacc[nt][3] - mn1);
                sum0 += sacc[nt][0] + sacc[nt][1];
                sum1 += sacc[nt][2] + sacc[nt][3];
                oacc[nt][0] *= cr0; oacc[nt][1] *= cr0;
                oacc[nt][2] *= cr1; oacc[nt][3] *= cr1;
            }
            sum0 += __shfl_xor_sync(0xffffffffu, sum0, 1);
            sum0 += __shfl_xor_sync(0xffffffffu, sum0, 2);
            sum1 += __shfl_xor_sync(0xffffffffu, sum1, 1);
            sum1 += __shfl_xor_sync(0xffffffffu, sum1, 2);
            l0 = l0 * cr0 + sum0;
            l1 = l1 * cr1 + sum1;
            m0 = mn0; m1 = mn1;

            #pragma unroll
            for (int j = 0; j < 4; j++) {
                unsigned pa_h[4], pa_l[4];
                #pragma unroll
                for (int half = 0; half < 2; half++) {
                    float x0 = sacc[2*j+half][0], x1 = sacc[2*j+half][1];
                    float x2 = sacc[2*j+half][2], x3 = sacc[2*j+half][3];
                    __nv_bfloat162 hA = __floats2bfloat162_rn(x0, x1);
                    __nv_bfloat162 hB = __floats2bfloat162_rn(x2, x3);
                    float2 fA = __bfloat1622float2(hA), fB = __bfloat1622float2(hB);
                    __nv_bfloat162 lA = __floats2bfloat162_rn(x0 - fA.x, x1 - fA.y);
                    __nv_bfloat162 lB = __floats2bfloat162_rn(x2 - fB.x, x3 - fB.y);
                    pa_h[half*2]     = *(unsigned*)&hA;
                    pa_h[half*2 + 1] = *(unsigned*)&hB;
                    pa_l[half*2]     = *(unsigned*)&lA;
                    pa_l[half*2 + 1] = *(unsigned*)&lB;
                }
                unsigned vb_h[8][2], vb_l[8][2];
                #pragma unroll
                for (int nt2 = 0; nt2 < 4; nt2++) {
                    int k  = j * 16 + (sub & 1) * 8 + li;
                    int ch = nt2 * 2 + (sub >> 1);
                    uint32_t a = stV + k * 128 + ((ch ^ (k & 7)) << 4);
                    unsigned r_[4];
                    LDSM4T(r_, a);
                    vb_h[nt2*2][0] = r_[0]; vb_h[nt2*2][1] = r_[1];
                    vb_h[nt2*2+1][0] = r_[2]; vb_h[nt2*2+1][1] = r_[3];
                    LDSM4T(r_, a + 8192);
                    vb_l[nt2*2][0] = r_[0]; vb_l[nt2*2][1] = r_[1];
                    vb_l[nt2*2+1][0] = r_[2]; vb_l[nt2*2+1][1] = r_[3];
                }
                #pragma unroll
                for (int nt = 0; nt < 8; nt++) {
                    mma16816(oacc[nt], pa_h, vb_h[nt]);
                    mma16816(oacc[nt], pa_h, vb_l[nt]);
                    mma16816(oacc[nt], pa_l, vb_h[nt]);
                }
            }
        }
    }

    float i0 = 1.f / l0, i1 = 1.f / l1;
    size_t row0 = (size_t)(b * CQ + q0 + w * 16 + gid) * 2048;
    size_t row1 = row0 + 8 * 2048;
    #pragma unroll
    for (int nt = 0; nt < 8; nt++) {
        int col = h * 64 + nt * 8 + 2 * tig;
        split_write(s_at_h, s_at_l, row0 + col, oacc[nt][0] * i0, oacc[nt][1] * i0);
        split_write(s_at_h, s_at_l, row1 + col, oacc[nt][2] * i1, oacc[nt][3] * i1);
    }
}

// ---------------- launch ----------------
extern "C" void kernel_launch(void* const* d_in, const int* in_sizes, int n_in,
                              void* d_out, int out_size) {
    const float* hs   = (const float*)d_in[0];
    const float* kb   = (const float*)d_in[1];
    const float* Wq   = (const float*)d_in[2];
    const float* Wk   = (const float*)d_in[3];
    const float* Wv   = (const float*)d_in[4];
    const float* Wo   = (const float*)d_in[5];
    const float* Wqn  = (const float*)d_in[6];
    const float* Wkbk = (const float*)d_in[7];
    const float* Wkbv = (const float*)d_in[8];
    const float* cosT = (const float*)d_in[9];
    const float* sinT = (const float*)d_in[10];
    const int*   pos  = (const int*)d_in[12];
    float* out = (float*)d_out;

    static cudaStream_t s2 = nullptr;
    static cudaEvent_t ev_fork = nullptr, ev_sel = nullptr, ev_bsplit = nullptr;
    static int attr_set = 0;
    if (!attr_set) {
        cudaFuncSetAttribute(proj_gemm, cudaFuncAttributeMaxDynamicSharedMemorySize, GSTG * STAGE_BYTES);
        cudaFuncSetAttribute(wo_gemm,   cudaFuncAttributeMaxDynamicSharedMemorySize, GSTG * STAGE_BYTES);
        cudaFuncSetAttribute(attn_tc_kernel, cudaFuncAttributeMaxDynamicSharedMemorySize, ATT_SMEM);
        cudaStreamCreateWithFlags(&s2, cudaStreamNonBlocking);
        cudaEventCreateWithFlags(&ev_fork,   cudaEventDisableTiming);
        cudaEventCreateWithFlags(&ev_sel,    cudaEventDisableTiming);
        cudaEventCreateWithFlags(&ev_bsplit, cudaEventDisableTiming);
        attr_set = 1;
    }

    const int M = CB * CQ;   // 2048
    const int SMEM = GSTG * STAGE_BYTES;

    // fork
    cudaEventRecord(ev_fork, 0);
    cudaStreamWaitEvent(s2, ev_fork, 0);

    // stream 0: main splits (hs + Wq/Wqn/Wk/Wv)
    splitA_kernel<<<7168, 256>>>(hs, Wq, Wk, Wv, Wqn);

    // stream s2: kb/wkb splits (gating proj) run concurrently with splitA
    splitB_kernel<<<2048, 256, 0, s2>>>(kb, Wkbk, Wkbv);
    cudaEventRecord(ev_bsplit, s2);

    // proj waits for both streams' splits
    cudaStreamWaitEvent(0, ev_bsplit, 0);
    proj_gemm<<<704, 256, SMEM, 0>>>(pos, cosT, sinT);

    // stream s2 (in proj's shadow): Wo split + factored KB selection
    wosplit_kernel<<<2048, 256, 0, s2>>>(Wo);
    hssum_kernel<<<dim3(CB, 16, 8), 128, 0, s2>>>(hs);
    qg_kernel<<<dim3(CB, 64), 512, 0, s2>>>(Wqn);
    qgc_kernel<<<CB, 512, 0, s2>>>();
    vk_kernel<<<dim3(CB, 128), 256, 0, s2>>>(Wkbk);
    scores_kernel<<<(CB * CKB) / 8, 256, 0, s2>>>(kb);
    topk_kernel<<<CB, 32, 0, s2>>>();
    cudaEventRecord(ev_sel, s2);

    // join: attention needs proj outputs (stream 0) + topk (s2)
    cudaStreamWaitEvent(0, ev_sel, 0);
    attn_tc_kernel<<<dim3(CQ / 64, CNH, CB), 128, ATT_SMEM>>>();

    // output projection (single launch, 256 CTAs)
    wo_gemm<<<dim3(CHID/128, M/128), 256, SMEM>>>(out, M, CHID, CHID);
}